// round 15
// baseline (speedup 1.0000x reference)
#include <cuda_runtime.h>
#include <cuda_bf16.h>
#include <cstdint>

#define BB 16
#define NN 1024
#define KKc 512
#define DIN 64
#define HH 256
#define FF 1024
#define LL 2
#define TOK (BB*NN)

typedef __nv_bfloat16 bf16;

#define WOFF_IN 0
#define WOFF_QKV (WOFF_IN + DIN*HH)
#define WOFF_O (WOFF_QKV + LL*HH*3*HH)
#define WOFF_1 (WOFF_O + LL*HH*HH)
#define WOFF_2 (WOFF_1 + LL*HH*FF)
#define WTOT (WOFF_2 + LL*FF*HH)

__device__ __align__(16) float g_h[TOK*HH];
__device__ __align__(16) bf16 g_xh[TOK*DIN], g_xl[TOK*DIN];
__device__ __align__(16) bf16 g_hbh[TOK*HH], g_hbl[TOK*HH];
__device__ __align__(16) bf16 g_qh[TOK*768], g_ql[TOK*768];
__device__ __align__(16) bf16 g_ah[TOK*HH], g_al[TOK*HH];
__device__ __align__(16) bf16 g_fh[TOK*FF], g_fl[TOK*FF];
__device__ __align__(16) bf16 g_wh[WTOT], g_wl[WTOT];

// ---------------- helpers ----------------
__device__ __forceinline__ uint32_t smem_u32(const void* p) {
    uint32_t a;
    asm("{ .reg .u64 t; cvta.to.shared.u64 t, %1; cvt.u32.u64 %0, t; }" : "=r"(a) : "l"(p));
    return a;
}
__device__ __forceinline__ void cp16(uint32_t d, const void* s) {
    asm volatile("cp.async.cg.shared.global [%0], [%1], 16;" :: "r"(d), "l"(s));
}
#define CPCOMMIT() asm volatile("cp.async.commit_group;" ::: "memory")
#define CPWAIT(n)  asm volatile("cp.async.wait_group %0;" :: "n"(n) : "memory")

__device__ __forceinline__ void ldm4(uint32_t* r, uint32_t a) {
    asm volatile("ldmatrix.sync.aligned.m8n8.x4.shared.b16 {%0,%1,%2,%3}, [%4];"
                 : "=r"(r[0]), "=r"(r[1]), "=r"(r[2]), "=r"(r[3]) : "r"(a));
}
__device__ __forceinline__ void ldm4t(uint32_t* r, uint32_t a) {
    asm volatile("ldmatrix.sync.aligned.m8n8.x4.trans.shared.b16 {%0,%1,%2,%3}, [%4];"
                 : "=r"(r[0]), "=r"(r[1]), "=r"(r[2]), "=r"(r[3]) : "r"(a));
}
__device__ __forceinline__ void mma_b16(float* c, const uint32_t* a, const uint32_t* b) {
    asm volatile("mma.sync.aligned.m16n8k16.row.col.f32.bf16.bf16.f32 "
                 "{%0,%1,%2,%3},{%4,%5,%6,%7},{%8,%9},{%0,%1,%2,%3};"
                 : "+f"(c[0]), "+f"(c[1]), "+f"(c[2]), "+f"(c[3])
                 : "r"(a[0]), "r"(a[1]), "r"(a[2]), "r"(a[3]), "r"(b[0]), "r"(b[1]));
}
__device__ __forceinline__ uint32_t bf2(float lo, float hi) {
    uint32_t r;
    asm("cvt.rn.bf16x2.f32 %0, %1, %2;" : "=r"(r) : "f"(hi), "f"(lo));
    return r;
}
__device__ __forceinline__ void split_pack(float a, float b, uint32_t& hi, uint32_t& lo) {
    float ah = __bfloat162float(__float2bfloat16(a));
    float bh = __bfloat162float(__float2bfloat16(b));
    hi = bf2(ah, bh); lo = bf2(a - ah, b - bh);
}

#define RS 40        // smem row stride (bf16): 80B, conflict-free ldmatrix
#define PLB 10240    // 128-row plane bytes
#define PLV 5120     // 64-row plane bytes
#define PL2 20480    // 256-row plane bytes

// ---------------- prep: weight transpose/split + x split ----------------
struct Seg { const float* s; bf16 *dh, *dl; int K, N, mode, ntiles; };
struct Segs { Seg seg[10]; };

__global__ void prep_kernel(Segs S) {
    Seg sg = S.seg[blockIdx.y];
    if ((int)blockIdx.x >= sg.ntiles) return;
    const int tx = threadIdx.x, ty = threadIdx.y;
    if (sg.mode == 1) {
        int off = blockIdx.x * 1024 + ty * 128 + tx * 4;
        float4 v = *(const float4*)(sg.s + off);
        float a[4] = {v.x, v.y, v.z, v.w};
        #pragma unroll
        for (int i = 0; i < 4; i++) {
            bf16 h = __float2bfloat16(a[i]);
            sg.dh[off + i] = h;
            sg.dl[off + i] = __float2bfloat16(a[i] - __bfloat162float(h));
        }
    } else {
        __shared__ float tile[32][33];
        int kt = blockIdx.x % (sg.K / 32), nt = blockIdx.x / (sg.K / 32);
        int k0 = kt * 32, n0 = nt * 32;
        #pragma unroll
        for (int i = 0; i < 4; i++)
            tile[ty * 4 + i][tx] = sg.s[(size_t)(k0 + ty * 4 + i) * sg.N + n0 + tx];
        __syncthreads();
        #pragma unroll
        for (int i = 0; i < 4; i++) {
            float v = tile[tx][ty * 4 + i];
            bf16 h = __float2bfloat16(v);
            size_t d = (size_t)(n0 + ty * 4 + i) * sg.K + k0 + tx;
            sg.dh[d] = h;
            sg.dl[d] = __float2bfloat16(v - __bfloat162float(h));
        }
    }
}

// ---------------- split-bf16 HMMA GEMM (round-13 proven) ----------------
__global__ __launch_bounds__(256, 2) void gemm_mma(
    const bf16* __restrict__ Ah, const bf16* __restrict__ Al,
    const bf16* __restrict__ Bh, const bf16* __restrict__ Bl,
    const float* __restrict__ bias, const float* __restrict__ res,
    float* __restrict__ Cf, bf16* __restrict__ Cbh, bf16* __restrict__ Cbl,
    int K, int N, int relu)
{
    extern __shared__ __align__(16) bf16 smr[];
    const int tid = threadIdx.x, lane = tid & 31, wid = tid >> 5;
    const int m0 = blockIdx.y << 7, n0 = blockIdx.x << 7;
    const int wm = (wid & 1) << 6, wn = (wid >> 1) << 5;
    const uint32_t sb = smem_u32(smr);
    const uint32_t sbA = sb, sbAl = sb + 2 * PLB;
    const uint32_t sbB = sb + 4 * PLB, sbBl = sb + 6 * PLB;

    float acc[4][4][4];
    #pragma unroll
    for (int a = 0; a < 4; a++)
        #pragma unroll
        for (int b = 0; b < 4; b++)
            #pragma unroll
            for (int c = 0; c < 4; c++) acc[a][b][c] = 0.f;

    const int nst = K >> 5;
    {
        #pragma unroll
        for (int i = 0; i < 4; i++) {
            int idx = tid + (i << 8);
            int pl = idx >> 9, rest = idx & 511;
            int r = rest >> 2, c8 = (rest & 3) << 3;
            uint32_t so = (uint32_t)(r * RS + c8) << 1;
            cp16((pl ? sbAl : sbA) + so, (pl ? Al : Ah) + (size_t)(m0 + r) * K + c8);
        }
        #pragma unroll
        for (int i = 0; i < 4; i++) {
            int idx = tid + (i << 8);
            int pl = idx >> 9, rest = idx & 511;
            int r = rest >> 2, c8 = (rest & 3) << 3;
            uint32_t so = (uint32_t)(r * RS + c8) << 1;
            cp16((pl ? sbBl : sbB) + so, (pl ? Bl : Bh) + (size_t)(n0 + r) * K + c8);
        }
        CPCOMMIT();
    }

    #pragma unroll 1
    for (int s = 0; s < nst; s++) {
        CPWAIT(0);
        __syncthreads();
        if (s + 1 < nst) {
            const int k0 = (s + 1) << 5, buf = (s + 1) & 1;
            #pragma unroll
            for (int i = 0; i < 4; i++) {
                int idx = tid + (i << 8);
                int pl = idx >> 9, rest = idx & 511;
                int r = rest >> 2, c8 = (rest & 3) << 3;
                uint32_t so = (uint32_t)(r * RS + c8) << 1;
                cp16((pl ? sbAl : sbA) + buf * PLB + so,
                     (pl ? Al : Ah) + (size_t)(m0 + r) * K + k0 + c8);
            }
            #pragma unroll
            for (int i = 0; i < 4; i++) {
                int idx = tid + (i << 8);
                int pl = idx >> 9, rest = idx & 511;
                int r = rest >> 2, c8 = (rest & 3) << 3;
                uint32_t so = (uint32_t)(r * RS + c8) << 1;
                cp16((pl ? sbBl : sbB) + buf * PLB + so,
                     (pl ? Bl : Bh) + (size_t)(n0 + r) * K + k0 + c8);
            }
            CPCOMMIT();
        }

        const int buf = s & 1;
        const uint32_t pAh = sbA + buf * PLB, pAl = sbAl + buf * PLB;
        const uint32_t pBh = sbB + buf * PLB, pBl = sbBl + buf * PLB;
        #pragma unroll
        for (int ks = 0; ks < 2; ks++) {
            uint32_t ah[4][4], al[4][4];
            #pragma unroll
            for (int mt = 0; mt < 4; mt++) {
                uint32_t off = (uint32_t)((wm + mt * 16 + (lane & 15)) * RS
                                          + ks * 16 + ((lane >> 4) << 3)) << 1;
                ldm4(ah[mt], pAh + off); ldm4(al[mt], pAl + off);
            }
            #pragma unroll
            for (int nt = 0; nt < 2; nt++) {
                uint32_t bh[4], bl[4];
                uint32_t off = (uint32_t)((wn + nt * 16 + (lane & 7) + ((lane >> 4) << 3)) * RS
                                          + ks * 16 + ((lane >> 3) & 1) * 8) << 1;
                ldm4(bh, pBh + off); ldm4(bl, pBl + off);
                #pragma unroll
                for (int mt = 0; mt < 4; mt++)
                    #pragma unroll
                    for (int t = 0; t < 2; t++) {
                        float* c = acc[mt][nt * 2 + t];
                        mma_b16(c, ah[mt], bh + 2 * t);
                        mma_b16(c, ah[mt], bl + 2 * t);
                        mma_b16(c, al[mt], bh + 2 * t);
                    }
            }
        }
    }

    #pragma unroll
    for (int mt = 0; mt < 4; mt++)
        #pragma unroll
        for (int nt = 0; nt < 4; nt++) {
            int r0 = m0 + wm + mt * 16 + (lane >> 2);
            int c  = n0 + wn + nt * 8 + ((lane & 3) << 1);
            float* a = acc[mt][nt];
            float b0 = bias[c], b1 = bias[c + 1];
            float v0 = a[0] + b0, v1 = a[1] + b1, v2 = a[2] + b0, v3 = a[3] + b1;
            if (res) {
                float2 q0 = *(const float2*)(res + (size_t)r0 * N + c);
                float2 q1 = *(const float2*)(res + (size_t)(r0 + 8) * N + c);
                v0 += q0.x; v1 += q0.y; v2 += q1.x; v3 += q1.y;
            }
            if (relu) {
                v0 = fmaxf(v0, 0.f); v1 = fmaxf(v1, 0.f);
                v2 = fmaxf(v2, 0.f); v3 = fmaxf(v3, 0.f);
            }
            if (Cf) {
                *(float2*)(Cf + (size_t)r0 * N + c)       = make_float2(v0, v1);
                *(float2*)(Cf + (size_t)(r0 + 8) * N + c) = make_float2(v2, v3);
            }
            if (Cbh) {
                uint32_t h0, l0, h1, l1;
                split_pack(v0, v1, h0, l0); split_pack(v2, v3, h1, l1);
                *(uint32_t*)(Cbh + (size_t)r0 * N + c) = h0;
                *(uint32_t*)(Cbl + (size_t)r0 * N + c) = l0;
                *(uint32_t*)(Cbh + (size_t)(r0 + 8) * N + c) = h1;
                *(uint32_t*)(Cbl + (size_t)(r0 + 8) * N + c) = l1;
            }
        }
}

// ---------------- GEMM + residual + LayerNorm fused (N = 256) --------------
// 64x256 block, 8 warps (2m x 4n, 32x64 warp tile). grid (TOK/64).
// smem: A 4*PLV, B 4*PL2, LN scratch 2KB -> 104448 B, 2 CTAs/SM.
__global__ __launch_bounds__(256, 2) void gemm_ln(
    const bf16* __restrict__ Ah, const bf16* __restrict__ Al,
    const bf16* __restrict__ Bh, const bf16* __restrict__ Bl,
    const float* __restrict__ bias, const float* __restrict__ gam,
    const float* __restrict__ bet,
    float* __restrict__ H, bf16* __restrict__ Obh, bf16* __restrict__ Obl,
    int K)
{
    extern __shared__ __align__(16) bf16 smr[];
    const int tid = threadIdx.x, lane = tid & 31, wid = tid >> 5;
    const int m0 = blockIdx.x << 6;
    const int wm = (wid & 1) << 5, wn = (wid >> 1) << 6;
    const uint32_t sb = smem_u32(smr);
    const uint32_t sbA = sb, sbAl = sb + 2 * PLV;
    const uint32_t sbB = sb + 4 * PLV, sbBl = sb + 4 * PLV + 2 * PL2;
    float* rsum = (float*)((char*)smr + 4 * PLV + 4 * PL2);  // [64][4]
    float* rsq  = rsum + 256;

    float acc[2][8][4];
    #pragma unroll
    for (int a = 0; a < 2; a++)
        #pragma unroll
        for (int b = 0; b < 8; b++)
            #pragma unroll
            for (int c = 0; c < 4; c++) acc[a][b][c] = 0.f;

    const int nst = K >> 5;
    {   // stage 0
        #pragma unroll
        for (int i = 0; i < 2; i++) {       // A: 512 chunks (64 rows, hi+lo)
            int idx = tid + (i << 8);
            int pl = idx >> 8, rest = idx & 255;
            int r = rest >> 2, c8 = (rest & 3) << 3;
            uint32_t so = (uint32_t)(r * RS + c8) << 1;
            cp16((pl ? sbAl : sbA) + so, (pl ? Al : Ah) + (size_t)(m0 + r) * K + c8);
        }
        #pragma unroll
        for (int i = 0; i < 8; i++) {       // B: 2048 chunks (256 rows)
            int idx = tid + (i << 8);
            int pl = idx >> 10, rest = idx & 1023;
            int r = rest >> 2, c8 = (rest & 3) << 3;
            uint32_t so = (uint32_t)(r * RS + c8) << 1;
            cp16((pl ? sbBl : sbB) + so, (pl ? Bl : Bh) + (size_t)r * K + c8);
        }
        CPCOMMIT();
    }

    #pragma unroll 1
    for (int s = 0; s < nst; s++) {
        CPWAIT(0);
        __syncthreads();
        if (s + 1 < nst) {
            const int k0 = (s + 1) << 5, buf = (s + 1) & 1;
            #pragma unroll
            for (int i = 0; i < 2; i++) {
                int idx = tid + (i << 8);
                int pl = idx >> 8, rest = idx & 255;
                int r = rest >> 2, c8 = (rest & 3) << 3;
                uint32_t so = (uint32_t)(r * RS + c8) << 1;
                cp16((pl ? sbAl : sbA) + buf * PLV + so,
                     (pl ? Al : Ah) + (size_t)(m0 + r) * K + k0 + c8);
            }
            #pragma unroll
            for (int i = 0; i < 8; i++) {
                int idx = tid + (i << 8);
                int pl = idx >> 10, rest = idx & 1023;
                int r = rest >> 2, c8 = (rest & 3) << 3;
                uint32_t so = (uint32_t)(r * RS + c8) << 1;
                cp16((pl ? sbBl : sbB) + buf * PL2 + so,
                     (pl ? Bl : Bh) + (size_t)r * K + k0 + c8);
            }
            CPCOMMIT();
        }

        const int buf = s & 1;
        const uint32_t pAh = sbA + buf * PLV, pAl = sbAl + buf * PLV;
        const uint32_t pBh = sbB + buf * PL2, pBl = sbBl + buf * PL2;
        #pragma unroll
        for (int ks = 0; ks < 2; ks++) {
            uint32_t ah[2][4], al[2][4];
            #pragma unroll
            for (int mt = 0; mt < 2; mt++) {
                uint32_t off = (uint32_t)((wm + mt * 16 + (lane & 15)) * RS
                                          + ks * 16 + ((lane >> 4) << 3)) << 1;
                ldm4(ah[mt], pAh + off); ldm4(al[mt], pAl + off);
            }
            #pragma unroll
            for (int nt = 0; nt < 4; nt++) {
                uint32_t bh[4], bl[4];
                uint32_t off = (uint32_t)((wn + nt * 16 + (lane & 7) + ((lane >> 4) << 3)) * RS
                                          + ks * 16 + ((lane >> 3) & 1) * 8) << 1;
                ldm4(bh, pBh + off); ldm4(bl, pBl + off);
                #pragma unroll
                for (int mt = 0; mt < 2; mt++)
                    #pragma unroll
                    for (int t = 0; t < 2; t++) {
                        float* c = acc[mt][nt * 2 + t];
                        mma_b16(c, ah[mt], bh + 2 * t);
                        mma_b16(c, ah[mt], bl + 2 * t);
                        mma_b16(c, al[mt], bh + 2 * t);
                    }
            }
        }
    }

    // epilogue: bias + residual + LN (rows fully inside CTA)
    const int wq = wid >> 1;
    #pragma unroll
    for (int mt = 0; mt < 2; mt++) {
        int r0 = m0 + wm + mt * 16 + (lane >> 2);
        float s0 = 0.f, q0 = 0.f, s1 = 0.f, q1 = 0.f;
        #pragma unroll
        for (int nt = 0; nt < 8; nt++) {
            int c = wn + nt * 8 + ((lane & 3) << 1);
            float* a = acc[mt][nt];
            float b0 = bias[c], b1 = bias[c + 1];
            float2 rr0 = *(const float2*)(H + (size_t)r0 * HH + c);
            float2 rr1 = *(const float2*)(H + (size_t)(r0 + 8) * HH + c);
            a[0] += b0 + rr0.x; a[1] += b1 + rr0.y;
            a[2] += b0 + rr1.x; a[3] += b1 + rr1.y;
            s0 += a[0] + a[1]; q0 += a[0]*a[0] + a[1]*a[1];
            s1 += a[2] + a[3]; q1 += a[2]*a[2] + a[3]*a[3];
        }
        s0 += __shfl_xor_sync(0xffffffffu, s0, 1); s0 += __shfl_xor_sync(0xffffffffu, s0, 2);
        q0 += __shfl_xor_sync(0xffffffffu, q0, 1); q0 += __shfl_xor_sync(0xffffffffu, q0, 2);
        s1 += __shfl_xor_sync(0xffffffffu, s1, 1); s1 += __shfl_xor_sync(0xffffffffu, s1, 2);
        q1 += __shfl_xor_sync(0xffffffffu, q1, 1); q1 += __shfl_xor_sync(0xffffffffu, q1, 2);
        if ((lane & 3) == 0) {
            int lr = wm + mt * 16 + (lane >> 2);
            rsum[lr * 4 + wq] = s0;       rsq[lr * 4 + wq] = q0;
            rsum[(lr + 8) * 4 + wq] = s1; rsq[(lr + 8) * 4 + wq] = q1;
        }
    }
    __syncthreads();

    #pragma unroll
    for (int mt = 0; mt < 2; mt++) {
        int lr = wm + mt * 16 + (lane >> 2);
        int gr0 = m0 + lr;
        float sm0 = rsum[lr*4] + rsum[lr*4+1] + rsum[lr*4+2] + rsum[lr*4+3];
        float sq0 = rsq[lr*4]  + rsq[lr*4+1]  + rsq[lr*4+2]  + rsq[lr*4+3];
        float sm1 = rsum[(lr+8)*4] + rsum[(lr+8)*4+1] + rsum[(lr+8)*4+2] + rsum[(lr+8)*4+3];
        float sq1 = rsq[(lr+8)*4]  + rsq[(lr+8)*4+1]  + rsq[(lr+8)*4+2]  + rsq[(lr+8)*4+3];
        float mu0 = sm0 * (1.f / HH), mu1 = sm1 * (1.f / HH);
        float iv0 = rsqrtf(sq0 * (1.f / HH) - mu0 * mu0 + 1e-5f);
        float iv1 = rsqrtf(sq1 * (1.f / HH) - mu1 * mu1 + 1e-5f);
        #pragma unroll
        for (int nt = 0; nt < 8; nt++) {
            int c = wn + nt * 8 + ((lane & 3) << 1);
            float* a = acc[mt][nt];
            float g0 = gam[c], g1 = gam[c + 1];
            float e0 = bet[c], e1 = bet[c + 1];
            float o0 = (a[0] - mu0) * iv0 * g0 + e0;
            float o1 = (a[1] - mu0) * iv0 * g1 + e1;
            float o2 = (a[2] - mu1) * iv1 * g0 + e0;
            float o3 = (a[3] - mu1) * iv1 * g1 + e1;
            *(float2*)(H + (size_t)gr0 * HH + c)       = make_float2(o0, o1);
            *(float2*)(H + (size_t)(gr0 + 8) * HH + c) = make_float2(o2, o3);
            uint32_t h0, l0, h1, l1;
            split_pack(o0, o1, h0, l0); split_pack(o2, o3, h1, l1);
            *(uint32_t*)(Obh + (size_t)gr0 * HH + c) = h0;
            *(uint32_t*)(Obl + (size_t)gr0 * HH + c) = l0;
            *(uint32_t*)(Obh + (size_t)(gr0 + 8) * HH + c) = h1;
            *(uint32_t*)(Obl + (size_t)(gr0 + 8) * HH + c) = l1;
        }
    }
}

// ---------------- fused HMMA flash attention (round-13 proven) -------------
__global__ __launch_bounds__(128, 4) void attn_mma(
    const bf16* __restrict__ qh, const bf16* __restrict__ ql,
    bf16* __restrict__ oh, bf16* __restrict__ ol)
{
    extern __shared__ __align__(16) bf16 smr[];
    const int tid = threadIdx.x, lane = tid & 31, wid = tid >> 5;
    const int bhn = blockIdx.y, b = bhn >> 3, h = bhn & 7;
    const int q0 = blockIdx.x << 7;
    const size_t base = (size_t)b * NN;
    const uint32_t sb = smem_u32(smr);
    const float SC = 0.17677669529663687f;

    #pragma unroll
    for (int i = 0; i < 8; i++) {
        int idx = tid + (i << 7);
        int pl = idx >> 9, rest = idx & 511;
        int r = rest >> 2, c8 = (rest & 3) << 3;
        uint32_t so = (uint32_t)(r * RS + c8) << 1;
        const bf16* src = (pl ? ql : qh) + (base + q0 + r) * 768 + h * 32 + c8;
        cp16(sb + pl * (2 * PLV) + so, src);
    }
    #pragma unroll
    for (int i = 0; i < 8; i++) {
        int idx = tid + (i << 7);
        int pl = idx >> 8, rest = idx & 255;
        int r = rest >> 2, c8 = (rest & 3) << 3;
        uint32_t so = (uint32_t)(r * RS + c8) << 1;
        int fo = (pl >> 1) ? 512 : 256;
        const bf16* src = ((pl & 1) ? ql : qh) + (base + r) * 768 + fo + h * 32 + c8;
        cp16(sb + 4 * PLV + pl * PLV + so, src);
    }
    CPCOMMIT();

    uint32_t qfh[2][2][4], qfl[2][2][4];
    float oacc[2][4][4];
    #pragma unroll
    for (int m = 0; m < 2; m++)
        #pragma unroll
        for (int a = 0; a < 4; a++)
            #pragma unroll
            for (int c = 0; c < 4; c++) oacc[m][a][c] = 0.f;
    float rs[2][2] = {{0.f, 0.f}, {0.f, 0.f}};

    CPWAIT(0);
    __syncthreads();
    #pragma unroll
    for (int mt = 0; mt < 2; mt++)
        #pragma unroll
        for (int ks = 0; ks < 2; ks++) {
            uint32_t off = (uint32_t)((wid * 32 + mt * 16 + (lane & 15)) * RS
                                      + ks * 16 + ((lane >> 4) << 3)) << 1;
            ldm4(qfh[mt][ks], sb + off);
            ldm4(qfl[mt][ks], sb + 2 * PLV + off);
        }

    for (int s = 0; s < 16; s++) {
        if (s > 0) CPWAIT(0);
        __syncthreads();
        if (s < 15) {
            const int kv0 = (s + 1) << 6;
            const uint32_t dstb = ((s + 1) & 1) ? sb : sb + 4 * PLV;
            #pragma unroll
            for (int i = 0; i < 8; i++) {
                int idx = tid + (i << 7);
                int pl = idx >> 8, rest = idx & 255;
                int r = rest >> 2, c8 = (rest & 3) << 3;
                uint32_t so = (uint32_t)(r * RS + c8) << 1;
                int fo = (pl >> 1) ? 512 : 256;
                const bf16* src = ((pl & 1) ? ql : qh) + (base + kv0 + r) * 768 + fo + h * 32 + c8;
                cp16(dstb + pl * PLV + so, src);
            }
            CPCOMMIT();
        }

        const uint32_t kH = (s & 1) ? sb : sb + 4 * PLV;
        const uint32_t kL = kH + PLV, vH = kH + 2 * PLV, vL = kH + 3 * PLV;

        #pragma unroll
        for (int kk = 0; kk < 4; kk++) {
            float sv[2][2][4];
            #pragma unroll
            for (int m = 0; m < 2; m++)
                #pragma unroll
                for (int t = 0; t < 2; t++)
                    #pragma unroll
                    for (int c = 0; c < 4; c++) sv[m][t][c] = 0.f;
            #pragma unroll
            for (int ks = 0; ks < 2; ks++) {
                uint32_t bh[4], bl[4];
                uint32_t off = (uint32_t)((kk * 16 + (lane & 7) + ((lane >> 4) << 3)) * RS
                                          + ks * 16 + ((lane >> 3) & 1) * 8) << 1;
                ldm4(bh, kH + off); ldm4(bl, kL + off);
                #pragma unroll
                for (int mt = 0; mt < 2; mt++)
                    #pragma unroll
                    for (int t = 0; t < 2; t++) {
                        float* c = sv[mt][t];
                        mma_b16(c, qfh[mt][ks], bh + 2 * t);
                        mma_b16(c, qfh[mt][ks], bl + 2 * t);
                        mma_b16(c, qfl[mt][ks], bh + 2 * t);
                    }
            }
            uint32_t va[4], vb[4], vc[4], vd[4];
            {
                uint32_t ro = kk * 16 + (lane & 7) + (((lane >> 3) & 1) << 3);
                uint32_t ofa = (uint32_t)(ro * RS + ((lane >> 4) << 3)) << 1;
                uint32_t ofb = (uint32_t)(ro * RS + 16 + ((lane >> 4) << 3)) << 1;
                ldm4t(va, vH + ofa); ldm4t(vb, vH + ofb);
                ldm4t(vc, vL + ofa); ldm4t(vd, vL + ofb);
            }
            #pragma unroll
            for (int mt = 0; mt < 2; mt++) {
                float e00 = __expf(sv[mt][0][0] * SC), e01 = __expf(sv[mt][0][1] * SC);
                float e02 = __expf(sv[mt][0][2] * SC), e03 = __expf(sv[mt][0][3] * SC);
                float e10 = __expf(sv[mt][1][0] * SC), e11 = __expf(sv[mt][1][1] * SC);
                float e12 = __expf(sv[mt][1][2] * SC), e13 = __expf(sv[mt][1][3] * SC);
                rs[mt][0] += e00 + e01 + e10 + e11;
                rs[mt][1] += e02 + e03 + e12 + e13;
                uint32_t pah[4], pal[4];
                split_pack(e00, e01, pah[0], pal[0]);
                split_pack(e02, e03, pah[1], pal[1]);
                split_pack(e10, e11, pah[2], pal[2]);
                split_pack(e12, e13, pah[3], pal[3]);
                float* o = (float*)oacc[mt];
                mma_b16(o + 0,  pah, va);     mma_b16(o + 0,  pah, vc);     mma_b16(o + 0,  pal, va);
                mma_b16(o + 4,  pah, va + 2); mma_b16(o + 4,  pah, vc + 2); mma_b16(o + 4,  pal, va + 2);
                mma_b16(o + 8,  pah, vb);     mma_b16(o + 8,  pah, vd);     mma_b16(o + 8,  pal, vb);
                mma_b16(o + 12, pah, vb + 2); mma_b16(o + 12, pah, vd + 2); mma_b16(o + 12, pal, vb + 2);
            }
        }
    }

    #pragma unroll
    for (int mt = 0; mt < 2; mt++) {
        float r0 = rs[mt][0], r1 = rs[mt][1];
        r0 += __shfl_xor_sync(0xffffffffu, r0, 1);
        r0 += __shfl_xor_sync(0xffffffffu, r0, 2);
        r1 += __shfl_xor_sync(0xffffffffu, r1, 1);
        r1 += __shfl_xor_sync(0xffffffffu, r1, 2);
        const float i0 = 1.f / r0, i1 = 1.f / r1;
        #pragma unroll
        for (int nt = 0; nt < 4; nt++) {
            int row = q0 + wid * 32 + mt * 16 + (lane >> 2);
            int c   = h * 32 + nt * 8 + ((lane & 3) << 1);
            float v0 = oacc[mt][nt][0] * i0, v1 = oacc[mt][nt][1] * i0;
            float v2 = oacc[mt][nt][2] * i1, v3 = oacc[mt][nt][3] * i1;
            uint32_t h0, l0, h1, l1;
            split_pack(v0, v1, h0, l0); split_pack(v2, v3, h1, l1);
            *(uint32_t*)(oh + (base + row) * HH + c) = h0;
            *(uint32_t*)(ol + (base + row) * HH + c) = l0;
            *(uint32_t*)(oh + (base + row + 8) * HH + c) = h1;
            *(uint32_t*)(ol + (base + row + 8) * HH + c) = l1;
        }
    }
}

// ---------------- fallback init ----------------
__global__ void init_out_kernel(float* __restrict__ out, int out_size)
{
    const int i = blockIdx.x * 256 + threadIdx.x;
    if (i < out_size) out[i] = 0.f;
}

// ---------------- allocation (round-11 proven) ----------------
__global__ __launch_bounds__(1024) void alloc_kernel(
    const float* __restrict__ enc, const int* __restrict__ sel,
    const float* __restrict__ Wc, const float* __restrict__ bc,
    float* __restrict__ outf, int both)
{
    __shared__ float part_s[4][HH];
    __shared__ float mean_s[HH], ctx_s[HH];
    __shared__ float sc_s[KKc];
    __shared__ float red_s[1024];
    __shared__ int   idx_s[KKc];
    __shared__ int   cnt_s[4];

    const int b = blockIdx.x, tid = threadIdx.x;
    float* bw = both ? (outf + BB * KKc) : outf;

    if (tid < KKc) idx_s[tid] = sel[b * KKc + tid];
    bw[b * NN + tid] = 0.f;
    __syncthreads();
    if (both && tid < KKc) outf[b * KKc + tid] = (float)idx_s[tid];

    const int c = tid & 255, grp = tid >> 8;
    {
        float acc = 0.f; int cnt = 0;
        const int kb = grp << 7;
        #pragma unroll 4
        for (int k = kb; k < kb + 128; k++) {
            const int idx = idx_s[k];
            if (idx < NN) { acc += enc[((size_t)b * NN + idx) * HH + c]; cnt++; }
        }
        part_s[grp][c] = acc;
        if (c == 0) cnt_s[grp] = cnt;
    }
    __syncthreads();
    const int cntT = cnt_s[0] + cnt_s[1] + cnt_s[2] + cnt_s[3];
    if (tid < HH)
        mean_s[tid] = ((part_s[0][tid] + part_s[1][tid]) + (part_s[2][tid] + part_s[3][tid]))
                      / (float)(cntT > 0 ? cntT : 1);
    __syncthreads();

    {
        float p = 0.f;
        const int ib = grp << 6;
        #pragma unroll 4
        for (int i = ib; i < ib + 64; i++) p += mean_s[i] * Wc[i * HH + c];
        part_s[grp][c] = p;
    }
    __syncthreads();
    if (tid < HH)
        ctx_s[tid] = ((part_s[0][tid] + part_s[1][tid]) + (part_s[2][tid] + part_s[3][tid]))
                     + bc[tid];
    __syncthreads();

    const int wid = tid >> 5, lane = tid & 31;
    for (int k = wid; k < KKc; k += 32) {
        const int idx = idx_s[k];
        float s = -1e30f;
        if (idx < NN) {
            const float* row = enc + ((size_t)b * NN + idx) * HH;
            float part = 0.f;
            #pragma unroll
            for (int i = 0; i < 8; i++) part += ctx_s[lane + i * 32] * row[lane + i * 32];
            #pragma unroll
            for (int o = 16; o; o >>= 1) part += __shfl_xor_sync(0xffffffffu, part, o);
            s = part;
        }
        if (lane == 0) sc_s[k] = s;
    }
    __syncthreads();

    red_s[tid] = (tid < KKc) ? sc_s[tid] : -1e30f;
    __syncthreads();
    for (int st = 512; st; st >>= 1) {
        if (tid < st) red_s[tid] = fmaxf(red_s[tid], red_s[tid + st]);
        __syncthreads();
    }
    const float m = red_s[0];
    __syncthreads();

    const int myidx = (tid < KKc) ? idx_s[tid] : NN;
    const float e = (myidx < NN) ? expf(sc_s[tid] - m) : 0.f;
    red_s[tid] = e;
    __syncthreads();
    for (int st = 512; st; st >>= 1) {
        if (tid < st) red_s[tid] += red_s[tid + st];
        __syncthreads();
    }
    const float denom = red_s[0];
    __syncthreads();

    float a = rintf(e / denom * 100.f);
    red_s[tid] = a;
    __syncthreads();
    for (int st = 512; st; st >>= 1) {
        if (tid < st) red_s[tid] += red_s[tid + st];
        __syncthreads();
    }
    const float diff = 100.f - red_s[0];
    __syncthreads();

    if (tid == 0 && myidx < NN) a += diff;
    if (myidx < NN) bw[b * NN + myidx] = a;
}

// ---------------- launch ----------------
extern "C" void kernel_launch(void* const* d_in, const int* in_sizes, int n_in,
                              void* d_out, int out_size)
{
    const float* x    = (const float*)d_in[0];
    const int*   sel  = (const int*)  d_in[1];
    const float* W_in = (const float*)d_in[2];
    const float* b_in = (const float*)d_in[3];
    const float* Wqkv = (const float*)d_in[4];
    const float* bqkv = (const float*)d_in[5];
    const float* Wo   = (const float*)d_in[6];
    const float* bo   = (const float*)d_in[7];
    const float* ln1g = (const float*)d_in[8];
    const float* ln1b = (const float*)d_in[9];
    const float* W1   = (const float*)d_in[10];
    const float* b1   = (const float*)d_in[11];
    const float* W2   = (const float*)d_in[12];
    const float* b2   = (const float*)d_in[13];
    const float* ln2g = (const float*)d_in[14];
    const float* ln2b = (const float*)d_in[15];
    const float* Wc   = (const float*)d_in[16];
    const float* bc   = (const float*)d_in[17];

    float *h;
    bf16 *xh, *xl, *hbh, *hbl, *qh, *ql, *ah, *al, *fh, *fl, *wh, *wl;
    cudaGetSymbolAddress((void**)&h,   g_h);
    cudaGetSymbolAddress((void**)&xh,  g_xh);  cudaGetSymbolAddress((void**)&xl,  g_xl);
    cudaGetSymbolAddress((void**)&hbh, g_hbh); cudaGetSymbolAddress((void**)&hbl, g_hbl);
    cudaGetSymbolAddress((void**)&qh,  g_qh);  cudaGetSymbolAddress((void**)&ql,  g_ql);
    cudaGetSymbolAddress((void**)&ah,  g_ah);  cudaGetSymbolAddress((void**)&al,  g_al);
    cudaGetSymbolAddress((void**)&fh,  g_fh);  cudaGetSymbolAddress((void**)&fl,  g_fl);
    cudaGetSymbolAddress((void**)&wh,  g_wh);  cudaGetSymbolAddress((void**)&wl,  g_wl);

    const int GSM  = 8 * PLB;                    // 81920
    const int ASM_ = 8 * PLV;                    // 40960
    const int GLSM = 4 * PLV + 4 * PL2 + 2048;   // 104448
    cudaFuncSetAttribute(gemm_mma, cudaFuncAttributeMaxDynamicSharedMemorySize, GSM);
    cudaFuncSetAttribute(attn_mma, cudaFuncAttributeMaxDynamicSharedMemorySize, ASM_);
    cudaFuncSetAttribute(gemm_ln,  cudaFuncAttributeMaxDynamicSharedMemorySize, GLSM);

    Segs S;
    S.seg[0] = { x, xh, xl, 0, 0, 1, (TOK * DIN) / 1024 };
    S.seg[1] = { W_in, wh + WOFF_IN, wl + WOFF_IN, DIN, HH, 0, (DIN/32)*(HH/32) };
    for (int l = 0; l < LL; l++) {
        S.seg[2+l] = { Wqkv + (size_t)l*HH*3*HH, wh + WOFF_QKV + l*HH*3*HH,
                       wl + WOFF_QKV + l*HH*3*HH, HH, 3*HH, 0, (HH/32)*(3*HH/32) };
        S.seg[4+l] = { Wo + (size_t)l*HH*HH, wh + WOFF_O + l*HH*HH,
                       wl + WOFF_O + l*HH*HH, HH, HH, 0, (HH/32)*(HH/32) };
        S.seg[6+l] = { W1 + (size_t)l*HH*FF, wh + WOFF_1 + l*HH*FF,
                       wl + WOFF_1 + l*HH*FF, HH, FF, 0, (HH/32)*(FF/32) };
        S.seg[8+l] = { W2 + (size_t)l*FF*HH, wh + WOFF_2 + l*FF*HH,
                       wl + WOFF_2 + l*FF*HH, FF, HH, 0, (FF/32)*(HH/32) };
    }
    prep_kernel<<<dim3(1024, 10), dim3(32, 8)>>>(S);

    gemm_mma<<<dim3(HH/128, TOK/128), 256, GSM>>>(
        xh, xl, wh + WOFF_IN, wl + WOFF_IN, b_in, nullptr, h, hbh, hbl, DIN, HH, 0);

    for (int l = 0; l < LL; l++) {
        gemm_mma<<<dim3(3*HH/128, TOK/128), 256, GSM>>>(
            hbh, hbl, wh + WOFF_QKV + l*HH*3*HH, wl + WOFF_QKV + l*HH*3*HH,
            bqkv + l*3*HH, nullptr, nullptr, qh, ql, HH, 3*HH, 0);
        attn_mma<<<dim3(NN/128, BB*8), 128, ASM_>>>(qh, ql, ah, al);
        gemm_ln<<<TOK/64, 256, GLSM>>>(
            ah, al, wh + WOFF_O + l*HH*HH, wl + WOFF_O + l*HH*HH,
            bo + l*HH, ln1g + l*HH, ln1b + l*HH, h, hbh, hbl, HH);
        gemm_mma<<<dim3(FF/128, TOK/128), 256, GSM>>>(
            hbh, hbl, wh + WOFF_1 + l*HH*FF, wl + WOFF_1 + l*HH*FF,
            b1 + l*FF, nullptr, nullptr, fh, fl, HH, FF, 1);
        gemm_ln<<<TOK/64, 256, GLSM>>>(
            fh, fl, wh + WOFF_2 + l*FF*HH, wl + WOFF_2 + l*FF*HH,
            b2 + l*HH, ln2g + l*HH, ln2b + l*HH, h, hbh, hbl, FF);
    }

    float* outf = (float*)d_out;
    const int idx_elems = BB * KKc, bw_elems = BB * NN;
    const int both = (out_size >= idx_elems + bw_elems) ? 1 : 0;

    const int covered = both ? (idx_elems + bw_elems) : bw_elems;
    if (out_size > covered)
        init_out_kernel<<<(out_size + 255) / 256, 256>>>(outf, out_size);

    alloc_kernel<<<BB, 1024>>>(h, sel, Wc, bc, outf, both);
}

// round 16
// speedup vs baseline: 1.0124x; 1.0124x over previous
#include <cuda_runtime.h>
#include <cuda_bf16.h>
#include <cstdint>

#define BB 16
#define NN 1024
#define KKc 512
#define DIN 64
#define HH 256
#define FF 1024
#define LL 2
#define TOK (BB*NN)

typedef __nv_bfloat16 bf16;

#define WOFF_IN 0
#define WOFF_QKV (WOFF_IN + DIN*HH)
#define WOFF_O (WOFF_QKV + LL*HH*3*HH)
#define WOFF_1 (WOFF_O + LL*HH*HH)
#define WOFF_2 (WOFF_1 + LL*HH*FF)
#define WTOT (WOFF_2 + LL*FF*HH)

__device__ __align__(16) float g_h[TOK*HH], g_tmp[TOK*HH];
__device__ __align__(16) bf16 g_xh[TOK*DIN], g_xl[TOK*DIN];
__device__ __align__(16) bf16 g_hbh[TOK*HH], g_hbl[TOK*HH];
__device__ __align__(16) bf16 g_qh[TOK*768], g_ql[TOK*768];
__device__ __align__(16) bf16 g_ah[TOK*HH], g_al[TOK*HH];
__device__ __align__(16) bf16 g_fh[TOK*FF], g_fl[TOK*FF];
__device__ __align__(16) bf16 g_wh[WTOT], g_wl[WTOT];

// ---------------- helpers ----------------
__device__ __forceinline__ uint32_t smem_u32(const void* p) {
    uint32_t a;
    asm("{ .reg .u64 t; cvta.to.shared.u64 t, %1; cvt.u32.u64 %0, t; }" : "=r"(a) : "l"(p));
    return a;
}
__device__ __forceinline__ void cp16(uint32_t d, const void* s) {
    asm volatile("cp.async.cg.shared.global [%0], [%1], 16;" :: "r"(d), "l"(s));
}
#define CPCOMMIT() asm volatile("cp.async.commit_group;" ::: "memory")
#define CPWAIT(n)  asm volatile("cp.async.wait_group %0;" :: "n"(n) : "memory")

__device__ __forceinline__ void ldm4(uint32_t* r, uint32_t a) {
    asm volatile("ldmatrix.sync.aligned.m8n8.x4.shared.b16 {%0,%1,%2,%3}, [%4];"
                 : "=r"(r[0]), "=r"(r[1]), "=r"(r[2]), "=r"(r[3]) : "r"(a));
}
__device__ __forceinline__ void ldm4t(uint32_t* r, uint32_t a) {
    asm volatile("ldmatrix.sync.aligned.m8n8.x4.trans.shared.b16 {%0,%1,%2,%3}, [%4];"
                 : "=r"(r[0]), "=r"(r[1]), "=r"(r[2]), "=r"(r[3]) : "r"(a));
}
__device__ __forceinline__ void mma_b16(float* c, const uint32_t* a, const uint32_t* b) {
    asm volatile("mma.sync.aligned.m16n8k16.row.col.f32.bf16.bf16.f32 "
                 "{%0,%1,%2,%3},{%4,%5,%6,%7},{%8,%9},{%0,%1,%2,%3};"
                 : "+f"(c[0]), "+f"(c[1]), "+f"(c[2]), "+f"(c[3])
                 : "r"(a[0]), "r"(a[1]), "r"(a[2]), "r"(a[3]), "r"(b[0]), "r"(b[1]));
}
__device__ __forceinline__ uint32_t bf2(float lo, float hi) {
    uint32_t r;
    asm("cvt.rn.bf16x2.f32 %0, %1, %2;" : "=r"(r) : "f"(hi), "f"(lo));
    return r;
}
__device__ __forceinline__ void split_pack(float a, float b, uint32_t& hi, uint32_t& lo) {
    float ah = __bfloat162float(__float2bfloat16(a));
    float bh = __bfloat162float(__float2bfloat16(b));
    hi = bf2(ah, bh); lo = bf2(a - ah, b - bh);
}

#define RS 40        // smem row stride (bf16): 80B, conflict-free ldmatrix
#define PLB 10240    // 128-row plane bytes
#define PLV 5120     // 64-row plane bytes

// ---------------- prep: weight transpose/split + x split ----------------
struct Seg { const float* s; bf16 *dh, *dl; int K, N, mode, ntiles; };
struct Segs { Seg seg[10]; };

__global__ void prep_kernel(Segs S) {
    Seg sg = S.seg[blockIdx.y];
    if ((int)blockIdx.x >= sg.ntiles) return;
    const int tx = threadIdx.x, ty = threadIdx.y;
    if (sg.mode == 1) {
        int off = blockIdx.x * 1024 + ty * 128 + tx * 4;
        float4 v = *(const float4*)(sg.s + off);
        float a[4] = {v.x, v.y, v.z, v.w};
        #pragma unroll
        for (int i = 0; i < 4; i++) {
            bf16 h = __float2bfloat16(a[i]);
            sg.dh[off + i] = h;
            sg.dl[off + i] = __float2bfloat16(a[i] - __bfloat162float(h));
        }
    } else {
        __shared__ float tile[32][33];
        int kt = blockIdx.x % (sg.K / 32), nt = blockIdx.x / (sg.K / 32);
        int k0 = kt * 32, n0 = nt * 32;
        #pragma unroll
        for (int i = 0; i < 4; i++)
            tile[ty * 4 + i][tx] = sg.s[(size_t)(k0 + ty * 4 + i) * sg.N + n0 + tx];
        __syncthreads();
        #pragma unroll
        for (int i = 0; i < 4; i++) {
            float v = tile[tx][ty * 4 + i];
            bf16 h = __float2bfloat16(v);
            size_t d = (size_t)(n0 + ty * 4 + i) * sg.K + k0 + tx;
            sg.dh[d] = h;
            sg.dl[d] = __float2bfloat16(v - __bfloat162float(h));
        }
    }
}

// ---------------- split-bf16 HMMA GEMM (round-13 proven) ----------------
__global__ __launch_bounds__(256, 2) void gemm_mma(
    const bf16* __restrict__ Ah, const bf16* __restrict__ Al,
    const bf16* __restrict__ Bh, const bf16* __restrict__ Bl,
    const float* __restrict__ bias, const float* __restrict__ res,
    float* __restrict__ Cf, bf16* __restrict__ Cbh, bf16* __restrict__ Cbl,
    int K, int N, int relu)
{
    extern __shared__ __align__(16) bf16 smr[];
    const int tid = threadIdx.x, lane = tid & 31, wid = tid >> 5;
    const int m0 = blockIdx.y << 7, n0 = blockIdx.x << 7;
    const int wm = (wid & 1) << 6, wn = (wid >> 1) << 5;
    const uint32_t sb = smem_u32(smr);
    const uint32_t sbA = sb, sbAl = sb + 2 * PLB;
    const uint32_t sbB = sb + 4 * PLB, sbBl = sb + 6 * PLB;

    float acc[4][4][4];
    #pragma unroll
    for (int a = 0; a < 4; a++)
        #pragma unroll
        for (int b = 0; b < 4; b++)
            #pragma unroll
            for (int c = 0; c < 4; c++) acc[a][b][c] = 0.f;

    const int nst = K >> 5;
    {
        #pragma unroll
        for (int i = 0; i < 4; i++) {
            int idx = tid + (i << 8);
            int pl = idx >> 9, rest = idx & 511;
            int r = rest >> 2, c8 = (rest & 3) << 3;
            uint32_t so = (uint32_t)(r * RS + c8) << 1;
            cp16((pl ? sbAl : sbA) + so, (pl ? Al : Ah) + (size_t)(m0 + r) * K + c8);
        }
        #pragma unroll
        for (int i = 0; i < 4; i++) {
            int idx = tid + (i << 8);
            int pl = idx >> 9, rest = idx & 511;
            int r = rest >> 2, c8 = (rest & 3) << 3;
            uint32_t so = (uint32_t)(r * RS + c8) << 1;
            cp16((pl ? sbBl : sbB) + so, (pl ? Bl : Bh) + (size_t)(n0 + r) * K + c8);
        }
        CPCOMMIT();
    }

    #pragma unroll 1
    for (int s = 0; s < nst; s++) {
        CPWAIT(0);
        __syncthreads();
        if (s + 1 < nst) {
            const int k0 = (s + 1) << 5, buf = (s + 1) & 1;
            #pragma unroll
            for (int i = 0; i < 4; i++) {
                int idx = tid + (i << 8);
                int pl = idx >> 9, rest = idx & 511;
                int r = rest >> 2, c8 = (rest & 3) << 3;
                uint32_t so = (uint32_t)(r * RS + c8) << 1;
                cp16((pl ? sbAl : sbA) + buf * PLB + so,
                     (pl ? Al : Ah) + (size_t)(m0 + r) * K + k0 + c8);
            }
            #pragma unroll
            for (int i = 0; i < 4; i++) {
                int idx = tid + (i << 8);
                int pl = idx >> 9, rest = idx & 511;
                int r = rest >> 2, c8 = (rest & 3) << 3;
                uint32_t so = (uint32_t)(r * RS + c8) << 1;
                cp16((pl ? sbBl : sbB) + buf * PLB + so,
                     (pl ? Bl : Bh) + (size_t)(n0 + r) * K + k0 + c8);
            }
            CPCOMMIT();
        }

        const int buf = s & 1;
        const uint32_t pAh = sbA + buf * PLB, pAl = sbAl + buf * PLB;
        const uint32_t pBh = sbB + buf * PLB, pBl = sbBl + buf * PLB;
        #pragma unroll
        for (int ks = 0; ks < 2; ks++) {
            uint32_t ah[4][4], al[4][4];
            #pragma unroll
            for (int mt = 0; mt < 4; mt++) {
                uint32_t off = (uint32_t)((wm + mt * 16 + (lane & 15)) * RS
                                          + ks * 16 + ((lane >> 4) << 3)) << 1;
                ldm4(ah[mt], pAh + off); ldm4(al[mt], pAl + off);
            }
            #pragma unroll
            for (int nt = 0; nt < 2; nt++) {
                uint32_t bh[4], bl[4];
                uint32_t off = (uint32_t)((wn + nt * 16 + (lane & 7) + ((lane >> 4) << 3)) * RS
                                          + ks * 16 + ((lane >> 3) & 1) * 8) << 1;
                ldm4(bh, pBh + off); ldm4(bl, pBl + off);
                #pragma unroll
                for (int mt = 0; mt < 4; mt++)
                    #pragma unroll
                    for (int t = 0; t < 2; t++) {
                        float* c = acc[mt][nt * 2 + t];
                        mma_b16(c, ah[mt], bh + 2 * t);
                        mma_b16(c, ah[mt], bl + 2 * t);
                        mma_b16(c, al[mt], bh + 2 * t);
                    }
            }
        }
    }

    #pragma unroll
    for (int mt = 0; mt < 4; mt++)
        #pragma unroll
        for (int nt = 0; nt < 4; nt++) {
            int r0 = m0 + wm + mt * 16 + (lane >> 2);
            int c  = n0 + wn + nt * 8 + ((lane & 3) << 1);
            float* a = acc[mt][nt];
            float b0 = bias[c], b1 = bias[c + 1];
            float v0 = a[0] + b0, v1 = a[1] + b1, v2 = a[2] + b0, v3 = a[3] + b1;
            if (res) {
                float2 q0 = *(const float2*)(res + (size_t)r0 * N + c);
                float2 q1 = *(const float2*)(res + (size_t)(r0 + 8) * N + c);
                v0 += q0.x; v1 += q0.y; v2 += q1.x; v3 += q1.y;
            }
            if (relu) {
                v0 = fmaxf(v0, 0.f); v1 = fmaxf(v1, 0.f);
                v2 = fmaxf(v2, 0.f); v3 = fmaxf(v3, 0.f);
            }
            if (Cf) {
                *(float2*)(Cf + (size_t)r0 * N + c)       = make_float2(v0, v1);
                *(float2*)(Cf + (size_t)(r0 + 8) * N + c) = make_float2(v2, v3);
            }
            if (Cbh) {
                uint32_t h0, l0, h1, l1;
                split_pack(v0, v1, h0, l0); split_pack(v2, v3, h1, l1);
                *(uint32_t*)(Cbh + (size_t)r0 * N + c) = h0;
                *(uint32_t*)(Cbl + (size_t)r0 * N + c) = l0;
                *(uint32_t*)(Cbh + (size_t)(r0 + 8) * N + c) = h1;
                *(uint32_t*)(Cbl + (size_t)(r0 + 8) * N + c) = l1;
            }
        }
}

// ---------------- fused HMMA flash attention (round-13 proven) -------------
__global__ __launch_bounds__(128, 4) void attn_mma(
    const bf16* __restrict__ qh, const bf16* __restrict__ ql,
    bf16* __restrict__ oh, bf16* __restrict__ ol)
{
    extern __shared__ __align__(16) bf16 smr[];
    const int tid = threadIdx.x, lane = tid & 31, wid = tid >> 5;
    const int bhn = blockIdx.y, b = bhn >> 3, h = bhn & 7;
    const int q0 = blockIdx.x << 7;
    const size_t base = (size_t)b * NN;
    const uint32_t sb = smem_u32(smr);
    const float SC = 0.17677669529663687f;

    #pragma unroll
    for (int i = 0; i < 8; i++) {
        int idx = tid + (i << 7);
        int pl = idx >> 9, rest = idx & 511;
        int r = rest >> 2, c8 = (rest & 3) << 3;
        uint32_t so = (uint32_t)(r * RS + c8) << 1;
        const bf16* src = (pl ? ql : qh) + (base + q0 + r) * 768 + h * 32 + c8;
        cp16(sb + pl * (2 * PLV) + so, src);
    }
    #pragma unroll
    for (int i = 0; i < 8; i++) {
        int idx = tid + (i << 7);
        int pl = idx >> 8, rest = idx & 255;
        int r = rest >> 2, c8 = (rest & 3) << 3;
        uint32_t so = (uint32_t)(r * RS + c8) << 1;
        int fo = (pl >> 1) ? 512 : 256;
        const bf16* src = ((pl & 1) ? ql : qh) + (base + r) * 768 + fo + h * 32 + c8;
        cp16(sb + 4 * PLV + pl * PLV + so, src);
    }
    CPCOMMIT();

    uint32_t qfh[2][2][4], qfl[2][2][4];
    float oacc[2][4][4];
    #pragma unroll
    for (int m = 0; m < 2; m++)
        #pragma unroll
        for (int a = 0; a < 4; a++)
            #pragma unroll
            for (int c = 0; c < 4; c++) oacc[m][a][c] = 0.f;
    float rs[2][2] = {{0.f, 0.f}, {0.f, 0.f}};

    CPWAIT(0);
    __syncthreads();
    #pragma unroll
    for (int mt = 0; mt < 2; mt++)
        #pragma unroll
        for (int ks = 0; ks < 2; ks++) {
            uint32_t off = (uint32_t)((wid * 32 + mt * 16 + (lane & 15)) * RS
                                      + ks * 16 + ((lane >> 4) << 3)) << 1;
            ldm4(qfh[mt][ks], sb + off);
            ldm4(qfl[mt][ks], sb + 2 * PLV + off);
        }

    for (int s = 0; s < 16; s++) {
        if (s > 0) CPWAIT(0);
        __syncthreads();
        if (s < 15) {
            const int kv0 = (s + 1) << 6;
            const uint32_t dstb = ((s + 1) & 1) ? sb : sb + 4 * PLV;
            #pragma unroll
            for (int i = 0; i < 8; i++) {
                int idx = tid + (i << 7);
                int pl = idx >> 8, rest = idx & 255;
                int r = rest >> 2, c8 = (rest & 3) << 3;
                uint32_t so = (uint32_t)(r * RS + c8) << 1;
                int fo = (pl >> 1) ? 512 : 256;
                const bf16* src = ((pl & 1) ? ql : qh) + (base + kv0 + r) * 768 + fo + h * 32 + c8;
                cp16(dstb + pl * PLV + so, src);
            }
            CPCOMMIT();
        }

        const uint32_t kH = (s & 1) ? sb : sb + 4 * PLV;
        const uint32_t kL = kH + PLV, vH = kH + 2 * PLV, vL = kH + 3 * PLV;

        #pragma unroll
        for (int kk = 0; kk < 4; kk++) {
            float sv[2][2][4];
            #pragma unroll
            for (int m = 0; m < 2; m++)
                #pragma unroll
                for (int t = 0; t < 2; t++)
                    #pragma unroll
                    for (int c = 0; c < 4; c++) sv[m][t][c] = 0.f;
            #pragma unroll
            for (int ks = 0; ks < 2; ks++) {
                uint32_t bh[4], bl[4];
                uint32_t off = (uint32_t)((kk * 16 + (lane & 7) + ((lane >> 4) << 3)) * RS
                                          + ks * 16 + ((lane >> 3) & 1) * 8) << 1;
                ldm4(bh, kH + off); ldm4(bl, kL + off);
                #pragma unroll
                for (int mt = 0; mt < 2; mt++)
                    #pragma unroll
                    for (int t = 0; t < 2; t++) {
                        float* c = sv[mt][t];
                        mma_b16(c, qfh[mt][ks], bh + 2 * t);
                        mma_b16(c, qfh[mt][ks], bl + 2 * t);
                        mma_b16(c, qfl[mt][ks], bh + 2 * t);
                    }
            }
            uint32_t va[4], vb[4], vc[4], vd[4];
            {
                uint32_t ro = kk * 16 + (lane & 7) + (((lane >> 3) & 1) << 3);
                uint32_t ofa = (uint32_t)(ro * RS + ((lane >> 4) << 3)) << 1;
                uint32_t ofb = (uint32_t)(ro * RS + 16 + ((lane >> 4) << 3)) << 1;
                ldm4t(va, vH + ofa); ldm4t(vb, vH + ofb);
                ldm4t(vc, vL + ofa); ldm4t(vd, vL + ofb);
            }
            #pragma unroll
            for (int mt = 0; mt < 2; mt++) {
                float e00 = __expf(sv[mt][0][0] * SC), e01 = __expf(sv[mt][0][1] * SC);
                float e02 = __expf(sv[mt][0][2] * SC), e03 = __expf(sv[mt][0][3] * SC);
                float e10 = __expf(sv[mt][1][0] * SC), e11 = __expf(sv[mt][1][1] * SC);
                float e12 = __expf(sv[mt][1][2] * SC), e13 = __expf(sv[mt][1][3] * SC);
                rs[mt][0] += e00 + e01 + e10 + e11;
                rs[mt][1] += e02 + e03 + e12 + e13;
                uint32_t pah[4], pal[4];
                split_pack(e00, e01, pah[0], pal[0]);
                split_pack(e02, e03, pah[1], pal[1]);
                split_pack(e10, e11, pah[2], pal[2]);
                split_pack(e12, e13, pah[3], pal[3]);
                float* o = (float*)oacc[mt];
                mma_b16(o + 0,  pah, va);     mma_b16(o + 0,  pah, vc);     mma_b16(o + 0,  pal, va);
                mma_b16(o + 4,  pah, va + 2); mma_b16(o + 4,  pah, vc + 2); mma_b16(o + 4,  pal, va + 2);
                mma_b16(o + 8,  pah, vb);     mma_b16(o + 8,  pah, vd);     mma_b16(o + 8,  pal, vb);
                mma_b16(o + 12, pah, vb + 2); mma_b16(o + 12, pah, vd + 2); mma_b16(o + 12, pal, vb + 2);
            }
        }
    }

    #pragma unroll
    for (int mt = 0; mt < 2; mt++) {
        float r0 = rs[mt][0], r1 = rs[mt][1];
        r0 += __shfl_xor_sync(0xffffffffu, r0, 1);
        r0 += __shfl_xor_sync(0xffffffffu, r0, 2);
        r1 += __shfl_xor_sync(0xffffffffu, r1, 1);
        r1 += __shfl_xor_sync(0xffffffffu, r1, 2);
        const float i0 = 1.f / r0, i1 = 1.f / r1;
        #pragma unroll
        for (int nt = 0; nt < 4; nt++) {
            int row = q0 + wid * 32 + mt * 16 + (lane >> 2);
            int c   = h * 32 + nt * 8 + ((lane & 3) << 1);
            float v0 = oacc[mt][nt][0] * i0, v1 = oacc[mt][nt][1] * i0;
            float v2 = oacc[mt][nt][2] * i1, v3 = oacc[mt][nt][3] * i1;
            uint32_t h0, l0, h1, l1;
            split_pack(v0, v1, h0, l0); split_pack(v2, v3, h1, l1);
            *(uint32_t*)(oh + (base + row) * HH + c) = h0;
            *(uint32_t*)(ol + (base + row) * HH + c) = l0;
            *(uint32_t*)(oh + (base + row + 8) * HH + c) = h1;
            *(uint32_t*)(ol + (base + row + 8) * HH + c) = l1;
        }
    }
}

// ---------------- LayerNorm (vectorized): fp32 in -> fp32 + bf16 hi/lo -----
// warp per row; each lane owns 8 contiguous columns (float4 x2 / uint4).
__global__ __launch_bounds__(256) void ln_kernel(
    const float* __restrict__ x, const float* __restrict__ gam,
    const float* __restrict__ bet, float* __restrict__ out,
    bf16* __restrict__ ohp, bf16* __restrict__ olp)
{
    const int row = blockIdx.x * 8 + (threadIdx.x >> 5);
    const int lane = threadIdx.x & 31;
    const int c0 = lane * 8;
    const float* xr = x + (size_t)row * HH + c0;
    float4 a0 = ((const float4*)xr)[0];
    float4 a1 = ((const float4*)xr)[1];
    float v[8] = {a0.x, a0.y, a0.z, a0.w, a1.x, a1.y, a1.z, a1.w};
    float sum = 0.f;
    #pragma unroll
    for (int i = 0; i < 8; i++) sum += v[i];
    #pragma unroll
    for (int o = 16; o; o >>= 1) sum += __shfl_xor_sync(0xffffffffu, sum, o);
    const float mean = sum * (1.f / HH);
    float var = 0.f;
    #pragma unroll
    for (int i = 0; i < 8; i++) { float d = v[i] - mean; var += d * d; }
    #pragma unroll
    for (int o = 16; o; o >>= 1) var += __shfl_xor_sync(0xffffffffu, var, o);
    const float inv = rsqrtf(var * (1.f / HH) + 1e-5f);

    float4 g0 = ((const float4*)(gam + c0))[0];
    float4 g1 = ((const float4*)(gam + c0))[1];
    float4 e0 = ((const float4*)(bet + c0))[0];
    float4 e1 = ((const float4*)(bet + c0))[1];
    float g[8] = {g0.x, g0.y, g0.z, g0.w, g1.x, g1.y, g1.z, g1.w};
    float e[8] = {e0.x, e0.y, e0.z, e0.w, e1.x, e1.y, e1.z, e1.w};

    float o8[8];
    #pragma unroll
    for (int i = 0; i < 8; i++) o8[i] = (v[i] - mean) * inv * g[i] + e[i];

    float* orow = out + (size_t)row * HH + c0;
    ((float4*)orow)[0] = make_float4(o8[0], o8[1], o8[2], o8[3]);
    ((float4*)orow)[1] = make_float4(o8[4], o8[5], o8[6], o8[7]);

    uint32_t ph[4], pl[4];
    #pragma unroll
    for (int t = 0; t < 4; t++) split_pack(o8[2*t], o8[2*t+1], ph[t], pl[t]);
    *(uint4*)(ohp + (size_t)row * HH + c0) = make_uint4(ph[0], ph[1], ph[2], ph[3]);
    *(uint4*)(olp + (size_t)row * HH + c0) = make_uint4(pl[0], pl[1], pl[2], pl[3]);
}

// ---------------- fallback init ----------------
__global__ void init_out_kernel(float* __restrict__ out, int out_size)
{
    const int i = blockIdx.x * 256 + threadIdx.x;
    if (i < out_size) out[i] = 0.f;
}

// ---------------- allocation (round-11 proven) ----------------
__global__ __launch_bounds__(1024) void alloc_kernel(
    const float* __restrict__ enc, const int* __restrict__ sel,
    const float* __restrict__ Wc, const float* __restrict__ bc,
    float* __restrict__ outf, int both)
{
    __shared__ float part_s[4][HH];
    __shared__ float mean_s[HH], ctx_s[HH];
    __shared__ float sc_s[KKc];
    __shared__ float red_s[1024];
    __shared__ int   idx_s[KKc];
    __shared__ int   cnt_s[4];

    const int b = blockIdx.x, tid = threadIdx.x;
    float* bw = both ? (outf + BB * KKc) : outf;

    if (tid < KKc) idx_s[tid] = sel[b * KKc + tid];
    bw[b * NN + tid] = 0.f;
    __syncthreads();
    if (both && tid < KKc) outf[b * KKc + tid] = (float)idx_s[tid];

    const int c = tid & 255, grp = tid >> 8;
    {
        float acc = 0.f; int cnt = 0;
        const int kb = grp << 7;
        #pragma unroll 4
        for (int k = kb; k < kb + 128; k++) {
            const int idx = idx_s[k];
            if (idx < NN) { acc += enc[((size_t)b * NN + idx) * HH + c]; cnt++; }
        }
        part_s[grp][c] = acc;
        if (c == 0) cnt_s[grp] = cnt;
    }
    __syncthreads();
    const int cntT = cnt_s[0] + cnt_s[1] + cnt_s[2] + cnt_s[3];
    if (tid < HH)
        mean_s[tid] = ((part_s[0][tid] + part_s[1][tid]) + (part_s[2][tid] + part_s[3][tid]))
                      / (float)(cntT > 0 ? cntT : 1);
    __syncthreads();

    {
        float p = 0.f;
        const int ib = grp << 6;
        #pragma unroll 4
        for (int i = ib; i < ib + 64; i++) p += mean_s[i] * Wc[i * HH + c];
        part_s[grp][c] = p;
    }
    __syncthreads();
    if (tid < HH)
        ctx_s[tid] = ((part_s[0][tid] + part_s[1][tid]) + (part_s[2][tid] + part_s[3][tid]))
                     + bc[tid];
    __syncthreads();

    const int wid = tid >> 5, lane = tid & 31;
    for (int k = wid; k < KKc; k += 32) {
        const int idx = idx_s[k];
        float s = -1e30f;
        if (idx < NN) {
            const float* row = enc + ((size_t)b * NN + idx) * HH;
            float part = 0.f;
            #pragma unroll
            for (int i = 0; i < 8; i++) part += ctx_s[lane + i * 32] * row[lane + i * 32];
            #pragma unroll
            for (int o = 16; o; o >>= 1) part += __shfl_xor_sync(0xffffffffu, part, o);
            s = part;
        }
        if (lane == 0) sc_s[k] = s;
    }
    __syncthreads();

    red_s[tid] = (tid < KKc) ? sc_s[tid] : -1e30f;
    __syncthreads();
    for (int st = 512; st; st >>= 1) {
        if (tid < st) red_s[tid] = fmaxf(red_s[tid], red_s[tid + st]);
        __syncthreads();
    }
    const float m = red_s[0];
    __syncthreads();

    const int myidx = (tid < KKc) ? idx_s[tid] : NN;
    const float e = (myidx < NN) ? expf(sc_s[tid] - m) : 0.f;
    red_s[tid] = e;
    __syncthreads();
    for (int st = 512; st; st >>= 1) {
        if (tid < st) red_s[tid] += red_s[tid + st];
        __syncthreads();
    }
    const float denom = red_s[0];
    __syncthreads();

    float a = rintf(e / denom * 100.f);
    red_s[tid] = a;
    __syncthreads();
    for (int st = 512; st; st >>= 1) {
        if (tid < st) red_s[tid] += red_s[tid + st];
        __syncthreads();
    }
    const float diff = 100.f - red_s[0];
    __syncthreads();

    if (tid == 0 && myidx < NN) a += diff;
    if (myidx < NN) bw[b * NN + myidx] = a;
}

// ---------------- launch ----------------
extern "C" void kernel_launch(void* const* d_in, const int* in_sizes, int n_in,
                              void* d_out, int out_size)
{
    const float* x    = (const float*)d_in[0];
    const int*   sel  = (const int*)  d_in[1];
    const float* W_in = (const float*)d_in[2];
    const float* b_in = (const float*)d_in[3];
    const float* Wqkv = (const float*)d_in[4];
    const float* bqkv = (const float*)d_in[5];
    const float* Wo   = (const float*)d_in[6];
    const float* bo   = (const float*)d_in[7];
    const float* ln1g = (const float*)d_in[8];
    const float* ln1b = (const float*)d_in[9];
    const float* W1   = (const float*)d_in[10];
    const float* b1   = (const float*)d_in[11];
    const float* W2   = (const float*)d_in[12];
    const float* b2   = (const float*)d_in[13];
    const float* ln2g = (const float*)d_in[14];
    const float* ln2b = (const float*)d_in[15];
    const float* Wc   = (const float*)d_in[16];
    const float* bc   = (const float*)d_in[17];

    float *h, *tmp;
    bf16 *xh, *xl, *hbh, *hbl, *qh, *ql, *ah, *al, *fh, *fl, *wh, *wl;
    cudaGetSymbolAddress((void**)&h,   g_h);   cudaGetSymbolAddress((void**)&tmp, g_tmp);
    cudaGetSymbolAddress((void**)&xh,  g_xh);  cudaGetSymbolAddress((void**)&xl,  g_xl);
    cudaGetSymbolAddress((void**)&hbh, g_hbh); cudaGetSymbolAddress((void**)&hbl, g_hbl);
    cudaGetSymbolAddress((void**)&qh,  g_qh);  cudaGetSymbolAddress((void**)&ql,  g_ql);
    cudaGetSymbolAddress((void**)&ah,  g_ah);  cudaGetSymbolAddress((void**)&al,  g_al);
    cudaGetSymbolAddress((void**)&fh,  g_fh);  cudaGetSymbolAddress((void**)&fl,  g_fl);
    cudaGetSymbolAddress((void**)&wh,  g_wh);  cudaGetSymbolAddress((void**)&wl,  g_wl);

    const int GSM  = 8 * PLB;     // 81920
    const int ASM_ = 8 * PLV;     // 40960
    cudaFuncSetAttribute(gemm_mma, cudaFuncAttributeMaxDynamicSharedMemorySize, GSM);
    cudaFuncSetAttribute(attn_mma, cudaFuncAttributeMaxDynamicSharedMemorySize, ASM_);

    Segs S;
    S.seg[0] = { x, xh, xl, 0, 0, 1, (TOK * DIN) / 1024 };
    S.seg[1] = { W_in, wh + WOFF_IN, wl + WOFF_IN, DIN, HH, 0, (DIN/32)*(HH/32) };
    for (int l = 0; l < LL; l++) {
        S.seg[2+l] = { Wqkv + (size_t)l*HH*3*HH, wh + WOFF_QKV + l*HH*3*HH,
                       wl + WOFF_QKV + l*HH*3*HH, HH, 3*HH, 0, (HH/32)*(3*HH/32) };
        S.seg[4+l] = { Wo + (size_t)l*HH*HH, wh + WOFF_O + l*HH*HH,
                       wl + WOFF_O + l*HH*HH, HH, HH, 0, (HH/32)*(HH/32) };
        S.seg[6+l] = { W1 + (size_t)l*HH*FF, wh + WOFF_1 + l*HH*FF,
                       wl + WOFF_1 + l*HH*FF, HH, FF, 0, (HH/32)*(FF/32) };
        S.seg[8+l] = { W2 + (size_t)l*FF*HH, wh + WOFF_2 + l*FF*HH,
                       wl + WOFF_2 + l*FF*HH, FF, HH, 0, (FF/32)*(HH/32) };
    }
    prep_kernel<<<dim3(1024, 10), dim3(32, 8)>>>(S);

    gemm_mma<<<dim3(HH/128, TOK/128), 256, GSM>>>(
        xh, xl, wh + WOFF_IN, wl + WOFF_IN, b_in, nullptr, h, hbh, hbl, DIN, HH, 0);

    for (int l = 0; l < LL; l++) {
        gemm_mma<<<dim3(3*HH/128, TOK/128), 256, GSM>>>(
            hbh, hbl, wh + WOFF_QKV + l*HH*3*HH, wl + WOFF_QKV + l*HH*3*HH,
            bqkv + l*3*HH, nullptr, nullptr, qh, ql, HH, 3*HH, 0);
        attn_mma<<<dim3(NN/128, BB*8), 128, ASM_>>>(qh, ql, ah, al);
        gemm_mma<<<dim3(HH/128, TOK/128), 256, GSM>>>(
            ah, al, wh + WOFF_O + l*HH*HH, wl + WOFF_O + l*HH*HH,
            bo + l*HH, h, tmp, nullptr, nullptr, HH, HH, 0);
        ln_kernel<<<TOK/8, 256>>>(tmp, ln1g + l*HH, ln1b + l*HH, h, hbh, hbl);
        gemm_mma<<<dim3(FF/128, TOK/128), 256, GSM>>>(
            hbh, hbl, wh + WOFF_1 + l*HH*FF, wl + WOFF_1 + l*HH*FF,
            b1 + l*FF, nullptr, nullptr, fh, fl, HH, FF, 1);
        gemm_mma<<<dim3(HH/128, TOK/128), 256, GSM>>>(
            fh, fl, wh + WOFF_2 + l*FF*HH, wl + WOFF_2 + l*FF*HH,
            b2 + l*HH, h, tmp, nullptr, nullptr, FF, HH, 0);
        ln_kernel<<<TOK/8, 256>>>(tmp, ln2g + l*HH, ln2b + l*HH, h, hbh, hbl);
    }

    float* outf = (float*)d_out;
    const int idx_elems = BB * KKc, bw_elems = BB * NN;
    const int both = (out_size >= idx_elems + bw_elems) ? 1 : 0;

    const int covered = both ? (idx_elems + bw_elems) : bw_elems;
    if (out_size > covered)
        init_out_kernel<<<(out_size + 255) / 256, 256>>>(outf, out_size);

    alloc_kernel<<<BB, 1024>>>(h, sel, Wc, bc, outf, both);
}

// round 17
// speedup vs baseline: 1.0246x; 1.0121x over previous
#include <cuda_runtime.h>
#include <cuda_bf16.h>
#include <cstdint>

#define BB 16
#define NN 1024
#define KKc 512
#define DIN 64
#define HH 256
#define FF 1024
#define LL 2
#define TOK (BB*NN)

typedef __nv_bfloat16 bf16;

#define WOFF_IN 0
#define WOFF_QKV (WOFF_IN + DIN*HH)
#define WOFF_O (WOFF_QKV + LL*HH*3*HH)
#define WOFF_1 (WOFF_O + LL*HH*HH)
#define WOFF_2 (WOFF_1 + LL*HH*FF)
#define WTOT (WOFF_2 + LL*FF*HH)

__device__ __align__(16) float g_h[TOK*HH], g_tmp[TOK*HH];
__device__ __align__(16) bf16 g_xh[TOK*DIN], g_xl[TOK*DIN];
__device__ __align__(16) bf16 g_hbh[TOK*HH], g_hbl[TOK*HH];
__device__ __align__(16) bf16 g_qh[TOK*768], g_ql[TOK*768];
__device__ __align__(16) bf16 g_ah[TOK*HH], g_al[TOK*HH];
__device__ __align__(16) bf16 g_fh[TOK*FF], g_fl[TOK*FF];
__device__ __align__(16) bf16 g_wh[WTOT], g_wl[WTOT];

// ---------------- helpers ----------------
__device__ __forceinline__ uint32_t smem_u32(const void* p) {
    uint32_t a;
    asm("{ .reg .u64 t; cvta.to.shared.u64 t, %1; cvt.u32.u64 %0, t; }" : "=r"(a) : "l"(p));
    return a;
}
__device__ __forceinline__ void cp16(uint32_t d, const void* s) {
    asm volatile("cp.async.cg.shared.global [%0], [%1], 16;" :: "r"(d), "l"(s));
}
#define CPCOMMIT() asm volatile("cp.async.commit_group;" ::: "memory")
#define CPWAIT(n)  asm volatile("cp.async.wait_group %0;" :: "n"(n) : "memory")

__device__ __forceinline__ void ldm4(uint32_t* r, uint32_t a) {
    asm volatile("ldmatrix.sync.aligned.m8n8.x4.shared.b16 {%0,%1,%2,%3}, [%4];"
                 : "=r"(r[0]), "=r"(r[1]), "=r"(r[2]), "=r"(r[3]) : "r"(a));
}
__device__ __forceinline__ void ldm4t(uint32_t* r, uint32_t a) {
    asm volatile("ldmatrix.sync.aligned.m8n8.x4.trans.shared.b16 {%0,%1,%2,%3}, [%4];"
                 : "=r"(r[0]), "=r"(r[1]), "=r"(r[2]), "=r"(r[3]) : "r"(a));
}
__device__ __forceinline__ void mma_b16(float* c, const uint32_t* a, const uint32_t* b) {
    asm volatile("mma.sync.aligned.m16n8k16.row.col.f32.bf16.bf16.f32 "
                 "{%0,%1,%2,%3},{%4,%5,%6,%7},{%8,%9},{%0,%1,%2,%3};"
                 : "+f"(c[0]), "+f"(c[1]), "+f"(c[2]), "+f"(c[3])
                 : "r"(a[0]), "r"(a[1]), "r"(a[2]), "r"(a[3]), "r"(b[0]), "r"(b[1]));
}
__device__ __forceinline__ uint32_t bf2(float lo, float hi) {
    uint32_t r;
    asm("cvt.rn.bf16x2.f32 %0, %1, %2;" : "=r"(r) : "f"(hi), "f"(lo));
    return r;
}
__device__ __forceinline__ void split_pack(float a, float b, uint32_t& hi, uint32_t& lo) {
    float ah = __bfloat162float(__float2bfloat16(a));
    float bh = __bfloat162float(__float2bfloat16(b));
    hi = bf2(ah, bh); lo = bf2(a - ah, b - bh);
}

#define RS 40        // smem row stride (bf16): 80B, conflict-free ldmatrix
#define PLB 10240    // 128-row plane bytes
#define PLV 5120     // 64-row plane bytes

// ---------------- prep: weight transpose/split + x split (compact grid) ----
struct Seg { const float* s; bf16 *dh, *dl; int K, N, mode, off; };
struct Segs { Seg seg[10]; int total; };

__global__ void prep_kernel(Segs S) {
    // find segment: seg[i].off <= blockIdx.x < seg[i+1].off (off[9+1]=total)
    int bid = blockIdx.x;
    int si = 0;
    #pragma unroll
    for (int i = 1; i < 10; i++) si += (bid >= S.seg[i].off) ? 1 : 0;
    Seg sg = S.seg[si];
    int t = bid - sg.off;
    const int tx = threadIdx.x, ty = threadIdx.y;
    if (sg.mode == 1) {
        int off = t * 1024 + ty * 128 + tx * 4;
        float4 v = *(const float4*)(sg.s + off);
        float a[4] = {v.x, v.y, v.z, v.w};
        #pragma unroll
        for (int i = 0; i < 4; i++) {
            bf16 h = __float2bfloat16(a[i]);
            sg.dh[off + i] = h;
            sg.dl[off + i] = __float2bfloat16(a[i] - __bfloat162float(h));
        }
    } else {
        __shared__ float tile[32][33];
        int kt = t % (sg.K / 32), nt = t / (sg.K / 32);
        int k0 = kt * 32, n0 = nt * 32;
        #pragma unroll
        for (int i = 0; i < 4; i++)
            tile[ty * 4 + i][tx] = sg.s[(size_t)(k0 + ty * 4 + i) * sg.N + n0 + tx];
        __syncthreads();
        #pragma unroll
        for (int i = 0; i < 4; i++) {
            float v = tile[tx][ty * 4 + i];
            bf16 h = __float2bfloat16(v);
            size_t d = (size_t)(n0 + ty * 4 + i) * sg.K + k0 + tx;
            sg.dh[d] = h;
            sg.dl[d] = __float2bfloat16(v - __bfloat162float(h));
        }
    }
}

// ---------------- split-bf16 HMMA GEMM (round-13 proven) ----------------
__global__ __launch_bounds__(256, 2) void gemm_mma(
    const bf16* __restrict__ Ah, const bf16* __restrict__ Al,
    const bf16* __restrict__ Bh, const bf16* __restrict__ Bl,
    const float* __restrict__ bias, const float* __restrict__ res,
    float* __restrict__ Cf, bf16* __restrict__ Cbh, bf16* __restrict__ Cbl,
    int K, int N, int relu)
{
    extern __shared__ __align__(16) bf16 smr[];
    const int tid = threadIdx.x, lane = tid & 31, wid = tid >> 5;
    const int m0 = blockIdx.y << 7, n0 = blockIdx.x << 7;
    const int wm = (wid & 1) << 6, wn = (wid >> 1) << 5;
    const uint32_t sb = smem_u32(smr);
    const uint32_t sbA = sb, sbAl = sb + 2 * PLB;
    const uint32_t sbB = sb + 4 * PLB, sbBl = sb + 6 * PLB;

    float acc[4][4][4];
    #pragma unroll
    for (int a = 0; a < 4; a++)
        #pragma unroll
        for (int b = 0; b < 4; b++)
            #pragma unroll
            for (int c = 0; c < 4; c++) acc[a][b][c] = 0.f;

    const int nst = K >> 5;
    {
        #pragma unroll
        for (int i = 0; i < 4; i++) {
            int idx = tid + (i << 8);
            int pl = idx >> 9, rest = idx & 511;
            int r = rest >> 2, c8 = (rest & 3) << 3;
            uint32_t so = (uint32_t)(r * RS + c8) << 1;
            cp16((pl ? sbAl : sbA) + so, (pl ? Al : Ah) + (size_t)(m0 + r) * K + c8);
        }
        #pragma unroll
        for (int i = 0; i < 4; i++) {
            int idx = tid + (i << 8);
            int pl = idx >> 9, rest = idx & 511;
            int r = rest >> 2, c8 = (rest & 3) << 3;
            uint32_t so = (uint32_t)(r * RS + c8) << 1;
            cp16((pl ? sbBl : sbB) + so, (pl ? Bl : Bh) + (size_t)(n0 + r) * K + c8);
        }
        CPCOMMIT();
    }

    #pragma unroll 1
    for (int s = 0; s < nst; s++) {
        CPWAIT(0);
        __syncthreads();
        if (s + 1 < nst) {
            const int k0 = (s + 1) << 5, buf = (s + 1) & 1;
            #pragma unroll
            for (int i = 0; i < 4; i++) {
                int idx = tid + (i << 8);
                int pl = idx >> 9, rest = idx & 511;
                int r = rest >> 2, c8 = (rest & 3) << 3;
                uint32_t so = (uint32_t)(r * RS + c8) << 1;
                cp16((pl ? sbAl : sbA) + buf * PLB + so,
                     (pl ? Al : Ah) + (size_t)(m0 + r) * K + k0 + c8);
            }
            #pragma unroll
            for (int i = 0; i < 4; i++) {
                int idx = tid + (i << 8);
                int pl = idx >> 9, rest = idx & 511;
                int r = rest >> 2, c8 = (rest & 3) << 3;
                uint32_t so = (uint32_t)(r * RS + c8) << 1;
                cp16((pl ? sbBl : sbB) + buf * PLB + so,
                     (pl ? Bl : Bh) + (size_t)(n0 + r) * K + k0 + c8);
            }
            CPCOMMIT();
        }

        const int buf = s & 1;
        const uint32_t pAh = sbA + buf * PLB, pAl = sbAl + buf * PLB;
        const uint32_t pBh = sbB + buf * PLB, pBl = sbBl + buf * PLB;
        #pragma unroll
        for (int ks = 0; ks < 2; ks++) {
            uint32_t ah[4][4], al[4][4];
            #pragma unroll
            for (int mt = 0; mt < 4; mt++) {
                uint32_t off = (uint32_t)((wm + mt * 16 + (lane & 15)) * RS
                                          + ks * 16 + ((lane >> 4) << 3)) << 1;
                ldm4(ah[mt], pAh + off); ldm4(al[mt], pAl + off);
            }
            #pragma unroll
            for (int nt = 0; nt < 2; nt++) {
                uint32_t bh[4], bl[4];
                uint32_t off = (uint32_t)((wn + nt * 16 + (lane & 7) + ((lane >> 4) << 3)) * RS
                                          + ks * 16 + ((lane >> 3) & 1) * 8) << 1;
                ldm4(bh, pBh + off); ldm4(bl, pBl + off);
                #pragma unroll
                for (int mt = 0; mt < 4; mt++)
                    #pragma unroll
                    for (int t = 0; t < 2; t++) {
                        float* c = acc[mt][nt * 2 + t];
                        mma_b16(c, ah[mt], bh + 2 * t);
                        mma_b16(c, ah[mt], bl + 2 * t);
                        mma_b16(c, al[mt], bh + 2 * t);
                    }
            }
        }
    }

    #pragma unroll
    for (int mt = 0; mt < 4; mt++)
        #pragma unroll
        for (int nt = 0; nt < 4; nt++) {
            int r0 = m0 + wm + mt * 16 + (lane >> 2);
            int c  = n0 + wn + nt * 8 + ((lane & 3) << 1);
            float* a = acc[mt][nt];
            float b0 = bias[c], b1 = bias[c + 1];
            float v0 = a[0] + b0, v1 = a[1] + b1, v2 = a[2] + b0, v3 = a[3] + b1;
            if (res) {
                float2 q0 = *(const float2*)(res + (size_t)r0 * N + c);
                float2 q1 = *(const float2*)(res + (size_t)(r0 + 8) * N + c);
                v0 += q0.x; v1 += q0.y; v2 += q1.x; v3 += q1.y;
            }
            if (relu) {
                v0 = fmaxf(v0, 0.f); v1 = fmaxf(v1, 0.f);
                v2 = fmaxf(v2, 0.f); v3 = fmaxf(v3, 0.f);
            }
            if (Cf) {
                *(float2*)(Cf + (size_t)r0 * N + c)       = make_float2(v0, v1);
                *(float2*)(Cf + (size_t)(r0 + 8) * N + c) = make_float2(v2, v3);
            }
            if (Cbh) {
                uint32_t h0, l0, h1, l1;
                split_pack(v0, v1, h0, l0); split_pack(v2, v3, h1, l1);
                *(uint32_t*)(Cbh + (size_t)r0 * N + c) = h0;
                *(uint32_t*)(Cbl + (size_t)r0 * N + c) = l0;
                *(uint32_t*)(Cbh + (size_t)(r0 + 8) * N + c) = h1;
                *(uint32_t*)(Cbl + (size_t)(r0 + 8) * N + c) = l1;
            }
        }
}

// ---------------- fused HMMA flash attention (round-13 proven) -------------
__global__ __launch_bounds__(128, 4) void attn_mma(
    const bf16* __restrict__ qh, const bf16* __restrict__ ql,
    bf16* __restrict__ oh, bf16* __restrict__ ol)
{
    extern __shared__ __align__(16) bf16 smr[];
    const int tid = threadIdx.x, lane = tid & 31, wid = tid >> 5;
    const int bhn = blockIdx.y, b = bhn >> 3, h = bhn & 7;
    const int q0 = blockIdx.x << 7;
    const size_t base = (size_t)b * NN;
    const uint32_t sb = smem_u32(smr);
    const float SC = 0.17677669529663687f;

    #pragma unroll
    for (int i = 0; i < 8; i++) {
        int idx = tid + (i << 7);
        int pl = idx >> 9, rest = idx & 511;
        int r = rest >> 2, c8 = (rest & 3) << 3;
        uint32_t so = (uint32_t)(r * RS + c8) << 1;
        const bf16* src = (pl ? ql : qh) + (base + q0 + r) * 768 + h * 32 + c8;
        cp16(sb + pl * (2 * PLV) + so, src);
    }
    #pragma unroll
    for (int i = 0; i < 8; i++) {
        int idx = tid + (i << 7);
        int pl = idx >> 8, rest = idx & 255;
        int r = rest >> 2, c8 = (rest & 3) << 3;
        uint32_t so = (uint32_t)(r * RS + c8) << 1;
        int fo = (pl >> 1) ? 512 : 256;
        const bf16* src = ((pl & 1) ? ql : qh) + (base + r) * 768 + fo + h * 32 + c8;
        cp16(sb + 4 * PLV + pl * PLV + so, src);
    }
    CPCOMMIT();

    uint32_t qfh[2][2][4], qfl[2][2][4];
    float oacc[2][4][4];
    #pragma unroll
    for (int m = 0; m < 2; m++)
        #pragma unroll
        for (int a = 0; a < 4; a++)
            #pragma unroll
            for (int c = 0; c < 4; c++) oacc[m][a][c] = 0.f;
    float rs[2][2] = {{0.f, 0.f}, {0.f, 0.f}};

    CPWAIT(0);
    __syncthreads();
    #pragma unroll
    for (int mt = 0; mt < 2; mt++)
        #pragma unroll
        for (int ks = 0; ks < 2; ks++) {
            uint32_t off = (uint32_t)((wid * 32 + mt * 16 + (lane & 15)) * RS
                                      + ks * 16 + ((lane >> 4) << 3)) << 1;
            ldm4(qfh[mt][ks], sb + off);
            ldm4(qfl[mt][ks], sb + 2 * PLV + off);
        }

    for (int s = 0; s < 16; s++) {
        if (s > 0) CPWAIT(0);
        __syncthreads();
        if (s < 15) {
            const int kv0 = (s + 1) << 6;
            const uint32_t dstb = ((s + 1) & 1) ? sb : sb + 4 * PLV;
            #pragma unroll
            for (int i = 0; i < 8; i++) {
                int idx = tid + (i << 7);
                int pl = idx >> 8, rest = idx & 255;
                int r = rest >> 2, c8 = (rest & 3) << 3;
                uint32_t so = (uint32_t)(r * RS + c8) << 1;
                int fo = (pl >> 1) ? 512 : 256;
                const bf16* src = ((pl & 1) ? ql : qh) + (base + kv0 + r) * 768 + fo + h * 32 + c8;
                cp16(dstb + pl * PLV + so, src);
            }
            CPCOMMIT();
        }

        const uint32_t kH = (s & 1) ? sb : sb + 4 * PLV;
        const uint32_t kL = kH + PLV, vH = kH + 2 * PLV, vL = kH + 3 * PLV;

        #pragma unroll
        for (int kk = 0; kk < 4; kk++) {
            float sv[2][2][4];
            #pragma unroll
            for (int m = 0; m < 2; m++)
                #pragma unroll
                for (int t = 0; t < 2; t++)
                    #pragma unroll
                    for (int c = 0; c < 4; c++) sv[m][t][c] = 0.f;
            #pragma unroll
            for (int ks = 0; ks < 2; ks++) {
                uint32_t bh[4], bl[4];
                uint32_t off = (uint32_t)((kk * 16 + (lane & 7) + ((lane >> 4) << 3)) * RS
                                          + ks * 16 + ((lane >> 3) & 1) * 8) << 1;
                ldm4(bh, kH + off); ldm4(bl, kL + off);
                #pragma unroll
                for (int mt = 0; mt < 2; mt++)
                    #pragma unroll
                    for (int t = 0; t < 2; t++) {
                        float* c = sv[mt][t];
                        mma_b16(c, qfh[mt][ks], bh + 2 * t);
                        mma_b16(c, qfh[mt][ks], bl + 2 * t);
                        mma_b16(c, qfl[mt][ks], bh + 2 * t);
                    }
            }
            uint32_t va[4], vb[4], vc[4], vd[4];
            {
                uint32_t ro = kk * 16 + (lane & 7) + (((lane >> 3) & 1) << 3);
                uint32_t ofa = (uint32_t)(ro * RS + ((lane >> 4) << 3)) << 1;
                uint32_t ofb = (uint32_t)(ro * RS + 16 + ((lane >> 4) << 3)) << 1;
                ldm4t(va, vH + ofa); ldm4t(vb, vH + ofb);
                ldm4t(vc, vL + ofa); ldm4t(vd, vL + ofb);
            }
            #pragma unroll
            for (int mt = 0; mt < 2; mt++) {
                float e00 = __expf(sv[mt][0][0] * SC), e01 = __expf(sv[mt][0][1] * SC);
                float e02 = __expf(sv[mt][0][2] * SC), e03 = __expf(sv[mt][0][3] * SC);
                float e10 = __expf(sv[mt][1][0] * SC), e11 = __expf(sv[mt][1][1] * SC);
                float e12 = __expf(sv[mt][1][2] * SC), e13 = __expf(sv[mt][1][3] * SC);
                rs[mt][0] += e00 + e01 + e10 + e11;
                rs[mt][1] += e02 + e03 + e12 + e13;
                uint32_t pah[4], pal[4];
                split_pack(e00, e01, pah[0], pal[0]);
                split_pack(e02, e03, pah[1], pal[1]);
                split_pack(e10, e11, pah[2], pal[2]);
                split_pack(e12, e13, pah[3], pal[3]);
                float* o = (float*)oacc[mt];
                mma_b16(o + 0,  pah, va);     mma_b16(o + 0,  pah, vc);     mma_b16(o + 0,  pal, va);
                mma_b16(o + 4,  pah, va + 2); mma_b16(o + 4,  pah, vc + 2); mma_b16(o + 4,  pal, va + 2);
                mma_b16(o + 8,  pah, vb);     mma_b16(o + 8,  pah, vd);     mma_b16(o + 8,  pal, vb);
                mma_b16(o + 12, pah, vb + 2); mma_b16(o + 12, pah, vd + 2); mma_b16(o + 12, pal, vb + 2);
            }
        }
    }

    #pragma unroll
    for (int mt = 0; mt < 2; mt++) {
        float r0 = rs[mt][0], r1 = rs[mt][1];
        r0 += __shfl_xor_sync(0xffffffffu, r0, 1);
        r0 += __shfl_xor_sync(0xffffffffu, r0, 2);
        r1 += __shfl_xor_sync(0xffffffffu, r1, 1);
        r1 += __shfl_xor_sync(0xffffffffu, r1, 2);
        const float i0 = 1.f / r0, i1 = 1.f / r1;
        #pragma unroll
        for (int nt = 0; nt < 4; nt++) {
            int row = q0 + wid * 32 + mt * 16 + (lane >> 2);
            int c   = h * 32 + nt * 8 + ((lane & 3) << 1);
            float v0 = oacc[mt][nt][0] * i0, v1 = oacc[mt][nt][1] * i0;
            float v2 = oacc[mt][nt][2] * i1, v3 = oacc[mt][nt][3] * i1;
            uint32_t h0, l0, h1, l1;
            split_pack(v0, v1, h0, l0); split_pack(v2, v3, h1, l1);
            *(uint32_t*)(oh + (base + row) * HH + c) = h0;
            *(uint32_t*)(ol + (base + row) * HH + c) = l0;
            *(uint32_t*)(oh + (base + row + 8) * HH + c) = h1;
            *(uint32_t*)(ol + (base + row + 8) * HH + c) = l1;
        }
    }
}

// ---------------- LayerNorm (round-13 proven scalar) ----------------
__global__ __launch_bounds__(256) void ln_kernel(
    const float* __restrict__ x, const float* __restrict__ gam,
    const float* __restrict__ bet, float* __restrict__ out,
    bf16* __restrict__ ohp, bf16* __restrict__ olp)
{
    const int row = blockIdx.x * 8 + (threadIdx.x >> 5);
    const int lane = threadIdx.x & 31;
    const float* xr = x + (size_t)row * HH;
    float v[8], sum = 0.f;
    #pragma unroll
    for (int i = 0; i < 8; i++) { v[i] = xr[lane + i * 32]; sum += v[i]; }
    #pragma unroll
    for (int o = 16; o; o >>= 1) sum += __shfl_xor_sync(0xffffffffu, sum, o);
    const float mean = sum * (1.f / HH);
    float var = 0.f;
    #pragma unroll
    for (int i = 0; i < 8; i++) { float d = v[i] - mean; var += d * d; }
    #pragma unroll
    for (int o = 16; o; o >>= 1) var += __shfl_xor_sync(0xffffffffu, var, o);
    const float inv = rsqrtf(var * (1.f / HH) + 1e-5f);
    #pragma unroll
    for (int i = 0; i < 8; i++) {
        const int c = lane + i * 32;
        float val = (v[i] - mean) * inv * gam[c] + bet[c];
        out[(size_t)row * HH + c] = val;
        bf16 hb = __float2bfloat16(val);
        ohp[(size_t)row * HH + c] = hb;
        olp[(size_t)row * HH + c] = __float2bfloat16(val - __bfloat162float(hb));
    }
}

// ---------------- fallback init ----------------
__global__ void init_out_kernel(float* __restrict__ out, int out_size)
{
    const int i = blockIdx.x * 256 + threadIdx.x;
    if (i < out_size) out[i] = 0.f;
}

// ---------------- allocation (round-11 proven) ----------------
__global__ __launch_bounds__(1024) void alloc_kernel(
    const float* __restrict__ enc, const int* __restrict__ sel,
    const float* __restrict__ Wc, const float* __restrict__ bc,
    float* __restrict__ outf, int both)
{
    __shared__ float part_s[4][HH];
    __shared__ float mean_s[HH], ctx_s[HH];
    __shared__ float sc_s[KKc];
    __shared__ float red_s[1024];
    __shared__ int   idx_s[KKc];
    __shared__ int   cnt_s[4];

    const int b = blockIdx.x, tid = threadIdx.x;
    float* bw = both ? (outf + BB * KKc) : outf;

    if (tid < KKc) idx_s[tid] = sel[b * KKc + tid];
    bw[b * NN + tid] = 0.f;
    __syncthreads();
    if (both && tid < KKc) outf[b * KKc + tid] = (float)idx_s[tid];

    const int c = tid & 255, grp = tid >> 8;
    {
        float acc = 0.f; int cnt = 0;
        const int kb = grp << 7;
        #pragma unroll 4
        for (int k = kb; k < kb + 128; k++) {
            const int idx = idx_s[k];
            if (idx < NN) { acc += enc[((size_t)b * NN + idx) * HH + c]; cnt++; }
        }
        part_s[grp][c] = acc;
        if (c == 0) cnt_s[grp] = cnt;
    }
    __syncthreads();
    const int cntT = cnt_s[0] + cnt_s[1] + cnt_s[2] + cnt_s[3];
    if (tid < HH)
        mean_s[tid] = ((part_s[0][tid] + part_s[1][tid]) + (part_s[2][tid] + part_s[3][tid]))
                      / (float)(cntT > 0 ? cntT : 1);
    __syncthreads();

    {
        float p = 0.f;
        const int ib = grp << 6;
        #pragma unroll 4
        for (int i = ib; i < ib + 64; i++) p += mean_s[i] * Wc[i * HH + c];
        part_s[grp][c] = p;
    }
    __syncthreads();
    if (tid < HH)
        ctx_s[tid] = ((part_s[0][tid] + part_s[1][tid]) + (part_s[2][tid] + part_s[3][tid]))
                     + bc[tid];
    __syncthreads();

    const int wid = tid >> 5, lane = tid & 31;
    for (int k = wid; k < KKc; k += 32) {
        const int idx = idx_s[k];
        float s = -1e30f;
        if (idx < NN) {
            const float* row = enc + ((size_t)b * NN + idx) * HH;
            float part = 0.f;
            #pragma unroll
            for (int i = 0; i < 8; i++) part += ctx_s[lane + i * 32] * row[lane + i * 32];
            #pragma unroll
            for (int o = 16; o; o >>= 1) part += __shfl_xor_sync(0xffffffffu, part, o);
            s = part;
        }
        if (lane == 0) sc_s[k] = s;
    }
    __syncthreads();

    red_s[tid] = (tid < KKc) ? sc_s[tid] : -1e30f;
    __syncthreads();
    for (int st = 512; st; st >>= 1) {
        if (tid < st) red_s[tid] = fmaxf(red_s[tid], red_s[tid + st]);
        __syncthreads();
    }
    const float m = red_s[0];
    __syncthreads();

    const int myidx = (tid < KKc) ? idx_s[tid] : NN;
    const float e = (myidx < NN) ? expf(sc_s[tid] - m) : 0.f;
    red_s[tid] = e;
    __syncthreads();
    for (int st = 512; st; st >>= 1) {
        if (tid < st) red_s[tid] += red_s[tid + st];
        __syncthreads();
    }
    const float denom = red_s[0];
    __syncthreads();

    float a = rintf(e / denom * 100.f);
    red_s[tid] = a;
    __syncthreads();
    for (int st = 512; st; st >>= 1) {
        if (tid < st) red_s[tid] += red_s[tid + st];
        __syncthreads();
    }
    const float diff = 100.f - red_s[0];
    __syncthreads();

    if (tid == 0 && myidx < NN) a += diff;
    if (myidx < NN) bw[b * NN + myidx] = a;
}

// ---------------- launch ----------------
extern "C" void kernel_launch(void* const* d_in, const int* in_sizes, int n_in,
                              void* d_out, int out_size)
{
    const float* x    = (const float*)d_in[0];
    const int*   sel  = (const int*)  d_in[1];
    const float* W_in = (const float*)d_in[2];
    const float* b_in = (const float*)d_in[3];
    const float* Wqkv = (const float*)d_in[4];
    const float* bqkv = (const float*)d_in[5];
    const float* Wo   = (const float*)d_in[6];
    const float* bo   = (const float*)d_in[7];
    const float* ln1g = (const float*)d_in[8];
    const float* ln1b = (const float*)d_in[9];
    const float* W1   = (const float*)d_in[10];
    const float* b1   = (const float*)d_in[11];
    const float* W2   = (const float*)d_in[12];
    const float* b2   = (const float*)d_in[13];
    const float* ln2g = (const float*)d_in[14];
    const float* ln2b = (const float*)d_in[15];
    const float* Wc   = (const float*)d_in[16];
    const float* bc   = (const float*)d_in[17];

    float *h, *tmp;
    bf16 *xh, *xl, *hbh, *hbl, *qh, *ql, *ah, *al, *fh, *fl, *wh, *wl;
    cudaGetSymbolAddress((void**)&h,   g_h);   cudaGetSymbolAddress((void**)&tmp, g_tmp);
    cudaGetSymbolAddress((void**)&xh,  g_xh);  cudaGetSymbolAddress((void**)&xl,  g_xl);
    cudaGetSymbolAddress((void**)&hbh, g_hbh); cudaGetSymbolAddress((void**)&hbl, g_hbl);
    cudaGetSymbolAddress((void**)&qh,  g_qh);  cudaGetSymbolAddress((void**)&ql,  g_ql);
    cudaGetSymbolAddress((void**)&ah,  g_ah);  cudaGetSymbolAddress((void**)&al,  g_al);
    cudaGetSymbolAddress((void**)&fh,  g_fh);  cudaGetSymbolAddress((void**)&fl,  g_fl);
    cudaGetSymbolAddress((void**)&wh,  g_wh);  cudaGetSymbolAddress((void**)&wl,  g_wl);

    const int GSM  = 8 * PLB;     // 81920
    const int ASM_ = 8 * PLV;     // 40960
    cudaFuncSetAttribute(gemm_mma, cudaFuncAttributeMaxDynamicSharedMemorySize, GSM);
    cudaFuncSetAttribute(attn_mma, cudaFuncAttributeMaxDynamicSharedMemorySize, ASM_);

    // compact prep grid: per-seg tile counts -> cumulative offsets
    Segs S;
    int ntl[10];
    S.seg[0] = { x, xh, xl, 0, 0, 1, 0 };                 ntl[0] = (TOK * DIN) / 1024;
    S.seg[1] = { W_in, wh + WOFF_IN, wl + WOFF_IN, DIN, HH, 0, 0 };
    ntl[1] = (DIN/32)*(HH/32);
    for (int l = 0; l < LL; l++) {
        S.seg[2+l] = { Wqkv + (size_t)l*HH*3*HH, wh + WOFF_QKV + l*HH*3*HH,
                       wl + WOFF_QKV + l*HH*3*HH, HH, 3*HH, 0, 0 };
        ntl[2+l] = (HH/32)*(3*HH/32);
        S.seg[4+l] = { Wo + (size_t)l*HH*HH, wh + WOFF_O + l*HH*HH,
                       wl + WOFF_O + l*HH*HH, HH, HH, 0, 0 };
        ntl[4+l] = (HH/32)*(HH/32);
        S.seg[6+l] = { W1 + (size_t)l*HH*FF, wh + WOFF_1 + l*HH*FF,
                       wl + WOFF_1 + l*HH*FF, HH, FF, 0, 0 };
        ntl[6+l] = (HH/32)*(FF/32);
        S.seg[8+l] = { W2 + (size_t)l*FF*HH, wh + WOFF_2 + l*FF*HH,
                       wl + WOFF_2 + l*FF*HH, FF, HH, 0, 0 };
        ntl[8+l] = (FF/32)*(HH/32);
    }
    int acc_off = 0;
    for (int i = 0; i < 10; i++) { S.seg[i].off = acc_off; acc_off += ntl[i]; }
    S.total = acc_off;
    prep_kernel<<<S.total, dim3(32, 8)>>>(S);

    gemm_mma<<<dim3(HH/128, TOK/128), 256, GSM>>>(
        xh, xl, wh + WOFF_IN, wl + WOFF_IN, b_in, nullptr, h, hbh, hbl, DIN, HH, 0);

    for (int l = 0; l < LL; l++) {
        gemm_mma<<<dim3(3*HH/128, TOK/128), 256, GSM>>>(
            hbh, hbl, wh + WOFF_QKV + l*HH*3*HH, wl + WOFF_QKV + l*HH*3*HH,
            bqkv + l*3*HH, nullptr, nullptr, qh, ql, HH, 3*HH, 0);
        attn_mma<<<dim3(NN/128, BB*8), 128, ASM_>>>(qh, ql, ah, al);
        gemm_mma<<<dim3(HH/128, TOK/128), 256, GSM>>>(
            ah, al, wh + WOFF_O + l*HH*HH, wl + WOFF_O + l*HH*HH,
            bo + l*HH, h, tmp, nullptr, nullptr, HH, HH, 0);
        ln_kernel<<<TOK/8, 256>>>(tmp, ln1g + l*HH, ln1b + l*HH, h, hbh, hbl);
        gemm_mma<<<dim3(FF/128, TOK/128), 256, GSM>>>(
            hbh, hbl, wh + WOFF_1 + l*HH*FF, wl + WOFF_1 + l*HH*FF,
            b1 + l*FF, nullptr, nullptr, fh, fl, HH, FF, 1);
        gemm_mma<<<dim3(HH/128, TOK/128), 256, GSM>>>(
            fh, fl, wh + WOFF_2 + l*FF*HH, wl + WOFF_2 + l*FF*HH,
            b2 + l*HH, h, tmp, nullptr, nullptr, FF, HH, 0);
        ln_kernel<<<TOK/8, 256>>>(tmp, ln2g + l*HH, ln2b + l*HH, h, hbh, hbl);
    }

    float* outf = (float*)d_out;
    const int idx_elems = BB * KKc, bw_elems = BB * NN;
    const int both = (out_size >= idx_elems + bw_elems) ? 1 : 0;

    const int covered = both ? (idx_elems + bw_elems) : bw_elems;
    if (out_size > covered)
        init_out_kernel<<<(out_size + 255) / 256, 256>>>(outf, out_size);

    alloc_kernel<<<BB, 1024>>>(h, sel, Wc, bc, outf, both);
}